// round 5
// baseline (speedup 1.0000x reference)
#include <cuda_runtime.h>
#include <math.h>
#include <stdint.h>

#define BB   8
#define NN   4096
#define SS   1024
#define KNBR 16
#define CIN  128
#define COUT 256
#define MROWS (BB*SS*KNBR)   /* 131072 */
#define BSR   (BB*SS)        /* 8192  */
#define NPTS  (BB*NN)        /* 32768 */

// ---------------- static device scratch (no allocs allowed) ----------------
__device__ float g_pos [(size_t)MROWS*COUT];  // pos_enc
__device__ float g_bufA[(size_t)MROWS*COUT];  // a1 -> att
__device__ float g_bufB[(size_t)MROWS*COUT];  // h1 -> h2
__device__ float g_kall[(size_t)NPTS*COUT];
__device__ float g_vall[(size_t)NPTS*COUT];
__device__ float g_q   [(size_t)BSR*COUT];
__device__ float g_res0[(size_t)BSR*COUT];
__device__ float g_res1[(size_t)BSR*COUT];
__device__ int   g_fps [BSR];
__device__ int   g_knn [MROWS];
__device__ float g_psum[64*COUT];
__device__ float g_psq [64*COUT];
__device__ float g_scale[COUT];
__device__ float g_shift[COUT];

// ---------------------------- FPS -----------------------------------------
__global__ __launch_bounds__(1024) void fps_kernel(const float* __restrict__ xyz,
                                                   float* __restrict__ newxyz)
{
    int b   = blockIdx.x;
    int tid = threadIdx.x;
    const float* base = xyz + (size_t)b * NN * 3;

    float px[4], py[4], pz[4], dist[4];
#pragma unroll
    for (int j = 0; j < 4; j++) {
        int i = tid * 4 + j;
        px[j] = base[i*3+0]; py[j] = base[i*3+1]; pz[j] = base[i*3+2];
        dist[j] = 1e10f;
    }

    __shared__ float swv[32];
    __shared__ int   swi[32];
    __shared__ int   sfar;

    int far  = 0;
    int lane = tid & 31, wid = tid >> 5;

    for (int s = 0; s < SS; s++) {
        float cx = __ldg(base + far*3 + 0);
        float cy = __ldg(base + far*3 + 1);
        float cz = __ldg(base + far*3 + 2);
        if (tid == 0) {
            g_fps[b*SS + s] = b*NN + far;
            newxyz[((size_t)b*SS + s)*3 + 0] = cx;
            newxyz[((size_t)b*SS + s)*3 + 1] = cy;
            newxyz[((size_t)b*SS + s)*3 + 2] = cz;
        }
        float bv = -1.0f; int bi = 0;
#pragma unroll
        for (int j = 0; j < 4; j++) {
            float dx = __fsub_rn(px[j], cx);
            float dy = __fsub_rn(py[j], cy);
            float dz = __fsub_rn(pz[j], cz);
            float d  = __fadd_rn(__fadd_rn(__fmul_rn(dx,dx), __fmul_rn(dy,dy)),
                                 __fmul_rn(dz,dz));
            dist[j] = fminf(dist[j], d);
            if (dist[j] > bv) { bv = dist[j]; bi = tid*4 + j; }
        }
#pragma unroll
        for (int off = 16; off; off >>= 1) {
            float ov = __shfl_xor_sync(0xffffffffu, bv, off);
            int   oi = __shfl_xor_sync(0xffffffffu, bi, off);
            if (ov > bv || (ov == bv && oi < bi)) { bv = ov; bi = oi; }
        }
        if (lane == 0) { swv[wid] = bv; swi[wid] = bi; }
        __syncthreads();
        if (tid < 32) {
            bv = swv[tid]; bi = swi[tid];
#pragma unroll
            for (int off = 16; off; off >>= 1) {
                float ov = __shfl_xor_sync(0xffffffffu, bv, off);
                int   oi = __shfl_xor_sync(0xffffffffu, bi, off);
                if (ov > bv || (ov == bv && oi < bi)) { bv = ov; bi = oi; }
            }
            if (tid == 0) sfar = bi;
        }
        __syncthreads();
        far = sfar;
    }
}

// ---------------------------- KNN -----------------------------------------
__global__ __launch_bounds__(256) void knn_kernel(const float* __restrict__ xyz,
                                                  const float* __restrict__ newxyz)
{
    int warp = (blockIdx.x * blockDim.x + threadIdx.x) >> 5;
    int lane = threadIdx.x & 31;
    int wloc = threadIdx.x >> 5;
    int b = warp / SS;
    const float* base = xyz + (size_t)b * NN * 3;

    float nx = newxyz[(size_t)warp*3+0];
    float ny = newxyz[(size_t)warp*3+1];
    float nz = newxyz[(size_t)warp*3+2];
    float ns = fmaf(nz, nz, fmaf(ny, ny, __fmul_rn(nx, nx)));

    float v[16]; int id[16];
#pragma unroll
    for (int t = 0; t < 16; t++) { v[t] = 3.4e38f; id[t] = 0x7fffffff; }

    for (int j = lane; j < NN; j += 32) {
        float x = base[j*3+0], y = base[j*3+1], z = base[j*3+2];
        float dot = fmaf(z, nz, fmaf(y, ny, __fmul_rn(x, nx)));
        float nq  = fmaf(z, z,  fmaf(y, y,  __fmul_rn(x, x)));
        float d   = __fadd_rn(__fsub_rn(ns, __fmul_rn(2.0f, dot)), nq);
        if (d < v[15]) {
            v[15] = d; id[15] = j;
#pragma unroll
            for (int t = 15; t > 0; t--) {
                if (v[t] < v[t-1] || (v[t] == v[t-1] && id[t] < id[t-1])) {
                    float tv = v[t]; v[t] = v[t-1]; v[t-1] = tv;
                    int   ti = id[t]; id[t] = id[t-1]; id[t-1] = ti;
                } else break;
            }
        }
    }

    __shared__ float smd[8][512];
    __shared__ int   smi[8][512];
#pragma unroll
    for (int t = 0; t < 16; t++) {
        smd[wloc][lane*16 + t] = v[t];
        smi[wloc][lane*16 + t] = id[t];
    }
    __syncwarp();

    int p = 0;
    for (int t = 0; t < 16; t++) {
        float cv = (p < 16) ? smd[wloc][lane*16 + p] : 3.4e38f;
        int   ci = (p < 16) ? smi[wloc][lane*16 + p] : 0x7fffffff;
        float mv = cv; int mi = ci;
#pragma unroll
        for (int off = 16; off; off >>= 1) {
            float ov = __shfl_xor_sync(0xffffffffu, mv, off);
            int   oi = __shfl_xor_sync(0xffffffffu, mi, off);
            if (ov < mv || (ov == mv && oi < mi)) { mv = ov; mi = oi; }
        }
        if (cv == mv && ci == mi) p++;
        if (lane == 0) g_knn[(size_t)warp*16 + t] = b*NN + mi;
        __syncwarp();
    }
}

// ------------------------- cp.async helpers --------------------------------
__device__ __forceinline__ void cp16(float* s, const float* g)
{
    unsigned sa = (unsigned)__cvta_generic_to_shared(s);
    asm volatile("cp.async.ca.shared.global [%0], [%1], 16;\n" :: "r"(sa), "l"(g));
}
#define CP_COMMIT() asm volatile("cp.async.commit_group;\n")
#define CP_WAIT0()  asm volatile("cp.async.wait_group 0;\n" ::: "memory")

// ---------------- double-buffered fp32 tiled GEMM --------------------------
// C[M,N=256 tilewise] = gather(A)[M,Kd] @ W[Kd,N] (+bias)(+relu)
// optional dual-write: C2[row,col] = qv[row>>4,col] - kall[knn[row],col] + C[row,col]
__global__ __launch_bounds__(256) void sgemm_db(
    const float* __restrict__ A, const int* __restrict__ rowmap,
    const float* __restrict__ W, const float* __restrict__ bias,
    float* __restrict__ C, int Kd, int N, int relu,
    const float* __restrict__ qv, const float* __restrict__ kall,
    const int* __restrict__ knn, float* __restrict__ C2)
{
    __shared__ float As[2][16][132];
    __shared__ float Bs[2][16][128];
    __shared__ int   rmap[128];

    int tid = threadIdx.x;
    int m0  = blockIdx.y * 128;
    int n0  = blockIdx.x * 128;

    if (tid < 128) rmap[tid] = rowmap ? rowmap[m0 + tid] : (m0 + tid);
    __syncthreads();

    // A load slots: thread handles row (tid>>1), 8 floats at k-offset (tid&1)*8
    int sr = tid >> 1;
    int sc = (tid & 1) * 8;
    const float* abase = A + (size_t)rmap[sr] * Kd + sc;

    // B load slots: two 16B chunks
    int kr0 = (tid*2) >> 5,   bc0 = ((tid*2) & 31) * 4;
    int kr1 = (tid*2+1) >> 5, bc1 = ((tid*2+1) & 31) * 4;

    // ---- prologue: tile 0 ----
    float4 ar0 = *(const float4*)(abase);
    float4 ar1 = *(const float4*)(abase + 4);
    cp16(&Bs[0][kr0][bc0], W + (size_t)kr0 * N + n0 + bc0);
    cp16(&Bs[0][kr1][bc1], W + (size_t)kr1 * N + n0 + bc1);
    CP_COMMIT();
    As[0][sc+0][sr] = ar0.x; As[0][sc+1][sr] = ar0.y;
    As[0][sc+2][sr] = ar0.z; As[0][sc+3][sr] = ar0.w;
    As[0][sc+4][sr] = ar1.x; As[0][sc+5][sr] = ar1.y;
    As[0][sc+6][sr] = ar1.z; As[0][sc+7][sr] = ar1.w;
    CP_WAIT0();
    __syncthreads();

    float acc[8][8];
#pragma unroll
    for (int i = 0; i < 8; i++)
#pragma unroll
        for (int j = 0; j < 8; j++) acc[i][j] = 0.0f;

    int tx = tid & 15, ty = tid >> 4;
    int nk = Kd >> 4;

    for (int t = 0; t < nk; t++) {
        int cur = t & 1, nxt = cur ^ 1;
        bool more = (t + 1) < nk;
        if (more) {
            int k0 = (t + 1) * 16;
            ar0 = *(const float4*)(abase + k0);
            ar1 = *(const float4*)(abase + k0 + 4);
            cp16(&Bs[nxt][kr0][bc0], W + (size_t)(k0+kr0) * N + n0 + bc0);
            cp16(&Bs[nxt][kr1][bc1], W + (size_t)(k0+kr1) * N + n0 + bc1);
            CP_COMMIT();
        }
#pragma unroll
        for (int kk = 0; kk < 16; kk++) {
            float a[8], bq[8];
            *(float4*)(a)    = *(float4*)(&As[cur][kk][ty*8]);
            *(float4*)(a+4)  = *(float4*)(&As[cur][kk][ty*8+4]);
            *(float4*)(bq)   = *(float4*)(&Bs[cur][kk][tx*8]);
            *(float4*)(bq+4) = *(float4*)(&Bs[cur][kk][tx*8+4]);
#pragma unroll
            for (int i = 0; i < 8; i++)
#pragma unroll
                for (int j = 0; j < 8; j++) acc[i][j] = fmaf(a[i], bq[j], acc[i][j]);
        }
        if (more) {
            As[nxt][sc+0][sr] = ar0.x; As[nxt][sc+1][sr] = ar0.y;
            As[nxt][sc+2][sr] = ar0.z; As[nxt][sc+3][sr] = ar0.w;
            As[nxt][sc+4][sr] = ar1.x; As[nxt][sc+5][sr] = ar1.y;
            As[nxt][sc+6][sr] = ar1.z; As[nxt][sc+7][sr] = ar1.w;
            CP_WAIT0();
        }
        __syncthreads();
    }

#pragma unroll
    for (int i = 0; i < 8; i++) {
        int row = m0 + ty*8 + i;
        int kn = 0;
        const float* qrow = nullptr;
        const float* krow = nullptr;
        if (C2) {
            kn = knn[row];
            qrow = qv + (size_t)(row >> 4) * N;
            krow = kall + (size_t)kn * N;
        }
#pragma unroll
        for (int j = 0; j < 8; j += 4) {
            int col = n0 + tx*8 + j;
            float4 o;
            o.x = acc[i][j+0]; o.y = acc[i][j+1]; o.z = acc[i][j+2]; o.w = acc[i][j+3];
            if (bias) { o.x += bias[col]; o.y += bias[col+1]; o.z += bias[col+2]; o.w += bias[col+3]; }
            if (relu) { o.x = fmaxf(o.x,0.f); o.y = fmaxf(o.y,0.f); o.z = fmaxf(o.z,0.f); o.w = fmaxf(o.w,0.f); }
            *(float4*)(C + (size_t)row*N + col) = o;
            if (C2) {
                float4 a1;
                a1.x = __fadd_rn(__fsub_rn(qrow[col+0], krow[col+0]), o.x);
                a1.y = __fadd_rn(__fsub_rn(qrow[col+1], krow[col+1]), o.y);
                a1.z = __fadd_rn(__fsub_rn(qrow[col+2], krow[col+2]), o.z);
                a1.w = __fadd_rn(__fsub_rn(qrow[col+3], krow[col+3]), o.w);
                *(float4*)(C2 + (size_t)row*N + col) = a1;
            }
        }
    }
}

// ------------------ pos-enc layer 1 (3 -> 256, relu) -----------------------
__global__ void h1_kernel(const float* __restrict__ xyz, const float* __restrict__ newxyz,
                          const float* __restrict__ dw1, const float* __restrict__ db1)
{
    int r = blockIdx.x;
    int c = threadIdx.x;
    int g  = g_knn[r];
    int bs = r >> 4;
    float cx = xyz[(size_t)g*3+0] - newxyz[(size_t)bs*3+0];
    float cy = xyz[(size_t)g*3+1] - newxyz[(size_t)bs*3+1];
    float cz = xyz[(size_t)g*3+2] - newxyz[(size_t)bs*3+2];
    float h = db1[c];
    h = fmaf(cx, dw1[0*COUT + c], h);
    h = fmaf(cy, dw1[1*COUT + c], h);
    h = fmaf(cz, dw1[2*COUT + c], h);
    g_bufB[(size_t)r*COUT + c] = fmaxf(h, 0.0f);
}

// --------------- softmax over K axis + weighted sum (v gathered) -----------
__global__ __launch_bounds__(256) void softmax_reduce_kernel()
{
    int bs = blockIdx.x;
    int c  = threadIdx.x;
    __shared__ int kn[16];
    if (c < 16) kn[c] = g_knn[bs*16 + c];
    __syncthreads();

    size_t base = (size_t)bs * KNBR * COUT + c;
    float a[16];
    float mx = -3.4e38f;
#pragma unroll
    for (int i = 0; i < 16; i++) {
        a[i] = g_bufA[base + (size_t)i*COUT] * 0.0625f;
        mx = fmaxf(mx, a[i]);
    }
    float se = 0.0f;
#pragma unroll
    for (int i = 0; i < 16; i++) { a[i] = expf(a[i] - mx); se += a[i]; }
    float inv = 1.0f / se;
    float acc = 0.0f;
#pragma unroll
    for (int i = 0; i < 16; i++) {
        float vp = g_vall[(size_t)kn[i]*COUT + c] + g_pos[base + (size_t)i*COUT];
        acc = fmaf(a[i]*inv, vp, acc);
    }
    g_res0[(size_t)bs*COUT + c] = acc;
}

// ---------------------------- BatchNorm ------------------------------------
__global__ void bn_partial_kernel()
{
    int blk = blockIdx.x;
    int c   = threadIdx.x;
    float s = 0.0f, q = 0.0f;
    for (int r = blk*128; r < blk*128 + 128; r++) {
        float x = g_res1[(size_t)r*COUT + c];
        s += x; q = fmaf(x, x, q);
    }
    g_psum[blk*COUT + c] = s;
    g_psq [blk*COUT + c] = q;
}

__global__ void bn_final_kernel(const float* __restrict__ bng, const float* __restrict__ bnb)
{
    int c = threadIdx.x;
    float s = 0.0f, q = 0.0f;
    for (int i = 0; i < 64; i++) { s += g_psum[i*COUT + c]; q += g_psq[i*COUT + c]; }
    float mean = s * (1.0f/(float)BSR);
    float var  = fmaxf(q * (1.0f/(float)BSR) - mean*mean, 0.0f);
    float sc   = bng[c] * rsqrtf(var + 1e-5f);
    g_scale[c] = sc;
    g_shift[c] = bnb[c] - mean * sc;
}

__global__ void bn_apply_kernel(float* __restrict__ out)
{
    size_t e = (size_t)blockIdx.x * blockDim.x + threadIdx.x;
    int c = (int)(e & 255);
    out[e] = fmaxf(fmaf(g_res1[e], g_scale[c], g_shift[c]), 0.0f);
}

// ------------------------------ launch --------------------------------------
extern "C" void kernel_launch(void* const* d_in, const int* in_sizes, int n_in,
                              void* d_out, int out_size)
{
    const float* xyz    = (const float*)d_in[0];
    const float* points = (const float*)d_in[1];
    const float* wq     = (const float*)d_in[2];
    const float* wk     = (const float*)d_in[3];
    const float* wv     = (const float*)d_in[4];
    const float* dw1    = (const float*)d_in[5];
    const float* db1    = (const float*)d_in[6];
    const float* dw2    = (const float*)d_in[7];
    const float* db2    = (const float*)d_in[8];
    const float* gw1    = (const float*)d_in[9];
    const float* gb1    = (const float*)d_in[10];
    const float* gw2    = (const float*)d_in[11];
    const float* gb2    = (const float*)d_in[12];
    const float* lw     = (const float*)d_in[13];
    const float* lb     = (const float*)d_in[14];
    const float* bng    = (const float*)d_in[15];
    const float* bnb    = (const float*)d_in[16];

    float* out     = (float*)d_out;
    float* newxyz  = out;
    float* res_out = out + (size_t)BSR*3;

    void *ppos, *pA, *pB, *pk, *pv, *pq, *pr0, *pr1, *pfps, *pknn;
    cudaGetSymbolAddress(&ppos, g_pos);
    cudaGetSymbolAddress(&pA,   g_bufA);
    cudaGetSymbolAddress(&pB,   g_bufB);
    cudaGetSymbolAddress(&pk,   g_kall);
    cudaGetSymbolAddress(&pv,   g_vall);
    cudaGetSymbolAddress(&pq,   g_q);
    cudaGetSymbolAddress(&pr0,  g_res0);
    cudaGetSymbolAddress(&pr1,  g_res1);
    cudaGetSymbolAddress(&pfps, g_fps);
    cudaGetSymbolAddress(&pknn, g_knn);

    // 1. FPS (+ writes new_xyz)
    fps_kernel<<<BB, 1024>>>(xyz, newxyz);
    // 2. KNN indices
    knn_kernel<<<BSR/8, 256>>>(xyz, newxyz);
    // 3/4. project ALL points once: k_all / v_all  (M=32768, Kd=128)
    sgemm_db<<<dim3(COUT/128, NPTS/128), 256>>>(points, nullptr, wk, nullptr,
        (float*)pk, CIN, COUT, 0, nullptr, nullptr, nullptr, nullptr);
    sgemm_db<<<dim3(COUT/128, NPTS/128), 256>>>(points, nullptr, wv, nullptr,
        (float*)pv, CIN, COUT, 0, nullptr, nullptr, nullptr, nullptr);
    // 5. q = gather(points, fps) @ wq  (M=8192)
    sgemm_db<<<dim3(COUT/128, BSR/128), 256>>>(points, (const int*)pfps, wq, nullptr,
        (float*)pq, CIN, COUT, 0, nullptr, nullptr, nullptr, nullptr);
    // 6. pos-enc layer 1 -> bufB
    h1_kernel<<<MROWS, 256>>>(xyz, newxyz, dw1, db1);
    // 7. pos = h1 @ dw2 + db2 -> g_pos;  fused dual-write a1 = q - k_gather + pos -> bufA
    sgemm_db<<<dim3(COUT/128, MROWS/128), 256>>>((const float*)pB, nullptr, dw2, db2,
        (float*)ppos, COUT, COUT, 0,
        (const float*)pq, (const float*)pk, (const int*)pknn, (float*)pA);
    // 8. h2 = relu(a1 @ gw1 + gb1) -> bufB
    sgemm_db<<<dim3(COUT/128, MROWS/128), 256>>>((const float*)pA, nullptr, gw1, gb1,
        (float*)pB, COUT, COUT, 1, nullptr, nullptr, nullptr, nullptr);
    // 9. att = h2 @ gw2 + gb2 -> bufA
    sgemm_db<<<dim3(COUT/128, MROWS/128), 256>>>((const float*)pB, nullptr, gw2, gb2,
        (float*)pA, COUT, COUT, 0, nullptr, nullptr, nullptr, nullptr);
    // 10. softmax over K + weighted sum of (v_gather + pos) -> res0
    softmax_reduce_kernel<<<BSR, 256>>>();
    // 11. res1 = res0 @ lw + lb
    sgemm_db<<<dim3(COUT/128, BSR/128), 256>>>((const float*)pr0, nullptr, lw, lb,
        (float*)pr1, COUT, COUT, 0, nullptr, nullptr, nullptr, nullptr);
    // 12. BatchNorm (training stats) + ReLU -> output
    bn_partial_kernel<<<64, 256>>>();
    bn_final_kernel<<<1, 256>>>(bng, bnb);
    bn_apply_kernel<<<(BSR*COUT)/1024, 1024>>>(res_out);
}

// round 6
// speedup vs baseline: 1.3058x; 1.3058x over previous
#include <cuda_runtime.h>
#include <cuda_bf16.h>
#include <math.h>
#include <stdint.h>

#define BB   8
#define NN   4096
#define SS   1024
#define KNBR 16
#define CIN  128
#define COUT 256
#define MROWS (BB*SS*KNBR)   /* 131072 */
#define BSR   (BB*SS)        /* 8192  */
#define NPTS  (BB*NN)        /* 32768 */

// ---------------- static device scratch (no allocs allowed) ----------------
__device__ float g_pos [(size_t)MROWS*COUT];  // pos_enc
__device__ float g_bufA[(size_t)MROWS*COUT];  // a1 -> att
__device__ float g_bufB[(size_t)MROWS*COUT];  // h1 -> h2
__device__ float g_kall[(size_t)NPTS*COUT];
__device__ float g_vall[(size_t)NPTS*COUT];
__device__ float g_q   [(size_t)BSR*COUT];
__device__ float g_res0[(size_t)BSR*COUT];
__device__ float g_res1[(size_t)BSR*COUT];
__device__ int   g_fps [BSR];
__device__ int   g_knn [MROWS];
__device__ float g_psum[64*COUT];
__device__ float g_psq [64*COUT];
__device__ float g_scale[COUT];
__device__ float g_shift[COUT];

// ---------------------------- FPS -----------------------------------------
__global__ __launch_bounds__(1024) void fps_kernel(const float* __restrict__ xyz,
                                                   float* __restrict__ newxyz)
{
    int b   = blockIdx.x;
    int tid = threadIdx.x;
    const float* base = xyz + (size_t)b * NN * 3;

    float px[4], py[4], pz[4], dist[4];
#pragma unroll
    for (int j = 0; j < 4; j++) {
        int i = tid * 4 + j;
        px[j] = base[i*3+0]; py[j] = base[i*3+1]; pz[j] = base[i*3+2];
        dist[j] = 1e10f;
    }

    __shared__ float swv[32];
    __shared__ int   swi[32];
    __shared__ int   sfar;

    int far  = 0;
    int lane = tid & 31, wid = tid >> 5;

    for (int s = 0; s < SS; s++) {
        float cx = __ldg(base + far*3 + 0);
        float cy = __ldg(base + far*3 + 1);
        float cz = __ldg(base + far*3 + 2);
        if (tid == 0) {
            g_fps[b*SS + s] = b*NN + far;
            newxyz[((size_t)b*SS + s)*3 + 0] = cx;
            newxyz[((size_t)b*SS + s)*3 + 1] = cy;
            newxyz[((size_t)b*SS + s)*3 + 2] = cz;
        }
        float bv = -1.0f; int bi = 0;
#pragma unroll
        for (int j = 0; j < 4; j++) {
            float dx = __fsub_rn(px[j], cx);
            float dy = __fsub_rn(py[j], cy);
            float dz = __fsub_rn(pz[j], cz);
            float d  = __fadd_rn(__fadd_rn(__fmul_rn(dx,dx), __fmul_rn(dy,dy)),
                                 __fmul_rn(dz,dz));
            dist[j] = fminf(dist[j], d);
            if (dist[j] > bv) { bv = dist[j]; bi = tid*4 + j; }
        }
#pragma unroll
        for (int off = 16; off; off >>= 1) {
            float ov = __shfl_xor_sync(0xffffffffu, bv, off);
            int   oi = __shfl_xor_sync(0xffffffffu, bi, off);
            if (ov > bv || (ov == bv && oi < bi)) { bv = ov; bi = oi; }
        }
        if (lane == 0) { swv[wid] = bv; swi[wid] = bi; }
        __syncthreads();
        if (tid < 32) {
            bv = swv[tid]; bi = swi[tid];
#pragma unroll
            for (int off = 16; off; off >>= 1) {
                float ov = __shfl_xor_sync(0xffffffffu, bv, off);
                int   oi = __shfl_xor_sync(0xffffffffu, bi, off);
                if (ov > bv || (ov == bv && oi < bi)) { bv = ov; bi = oi; }
            }
            if (tid == 0) sfar = bi;
        }
        __syncthreads();
        far = sfar;
    }
}

// ---------------------------- KNN -----------------------------------------
__global__ __launch_bounds__(256) void knn_kernel(const float* __restrict__ xyz,
                                                  const float* __restrict__ newxyz)
{
    int warp = (blockIdx.x * blockDim.x + threadIdx.x) >> 5;
    int lane = threadIdx.x & 31;
    int wloc = threadIdx.x >> 5;
    int b = warp / SS;
    const float* base = xyz + (size_t)b * NN * 3;

    float nx = newxyz[(size_t)warp*3+0];
    float ny = newxyz[(size_t)warp*3+1];
    float nz = newxyz[(size_t)warp*3+2];
    float ns = fmaf(nz, nz, fmaf(ny, ny, __fmul_rn(nx, nx)));

    float v[16]; int id[16];
#pragma unroll
    for (int t = 0; t < 16; t++) { v[t] = 3.4e38f; id[t] = 0x7fffffff; }

    for (int j = lane; j < NN; j += 32) {
        float x = base[j*3+0], y = base[j*3+1], z = base[j*3+2];
        float dot = fmaf(z, nz, fmaf(y, ny, __fmul_rn(x, nx)));
        float nq  = fmaf(z, z,  fmaf(y, y,  __fmul_rn(x, x)));
        float d   = __fadd_rn(__fsub_rn(ns, __fmul_rn(2.0f, dot)), nq);
        if (d < v[15]) {
            v[15] = d; id[15] = j;
#pragma unroll
            for (int t = 15; t > 0; t--) {
                if (v[t] < v[t-1] || (v[t] == v[t-1] && id[t] < id[t-1])) {
                    float tv = v[t]; v[t] = v[t-1]; v[t-1] = tv;
                    int   ti = id[t]; id[t] = id[t-1]; id[t-1] = ti;
                } else break;
            }
        }
    }

    __shared__ float smd[8][512];
    __shared__ int   smi[8][512];
#pragma unroll
    for (int t = 0; t < 16; t++) {
        smd[wloc][lane*16 + t] = v[t];
        smi[wloc][lane*16 + t] = id[t];
    }
    __syncwarp();

    int p = 0;
    for (int t = 0; t < 16; t++) {
        float cv = (p < 16) ? smd[wloc][lane*16 + p] : 3.4e38f;
        int   ci = (p < 16) ? smi[wloc][lane*16 + p] : 0x7fffffff;
        float mv = cv; int mi = ci;
#pragma unroll
        for (int off = 16; off; off >>= 1) {
            float ov = __shfl_xor_sync(0xffffffffu, mv, off);
            int   oi = __shfl_xor_sync(0xffffffffu, mi, off);
            if (ov < mv || (ov == mv && oi < mi)) { mv = ov; mi = oi; }
        }
        if (cv == mv && ci == mi) p++;
        if (lane == 0) g_knn[(size_t)warp*16 + t] = b*NN + mi;
        __syncwarp();
    }
}

// -------------------- bf16 split + mma helpers ------------------------------
__device__ __forceinline__ void split2(float x0, float x1, uint32_t& hi, uint32_t& lo)
{
    __nv_bfloat16 h0 = __float2bfloat16(x0);
    __nv_bfloat16 h1 = __float2bfloat16(x1);
    float r0 = __fsub_rn(x0, __bfloat162float(h0));
    float r1 = __fsub_rn(x1, __bfloat162float(h1));
    __nv_bfloat16 l0 = __float2bfloat16(r0);
    __nv_bfloat16 l1 = __float2bfloat16(r1);
    hi = (uint32_t)__bfloat16_as_ushort(h0) | ((uint32_t)__bfloat16_as_ushort(h1) << 16);
    lo = (uint32_t)__bfloat16_as_ushort(l0) | ((uint32_t)__bfloat16_as_ushort(l1) << 16);
}

__device__ __forceinline__ void ldsm_x4(uint32_t* r, const void* p)
{
    uint32_t a = (uint32_t)__cvta_generic_to_shared(p);
    asm volatile("ldmatrix.sync.aligned.m8n8.x4.shared.b16 {%0,%1,%2,%3}, [%4];"
                 : "=r"(r[0]), "=r"(r[1]), "=r"(r[2]), "=r"(r[3]) : "r"(a));
}

__device__ __forceinline__ void ldsm_x4_t(uint32_t* r, const void* p)
{
    uint32_t a = (uint32_t)__cvta_generic_to_shared(p);
    asm volatile("ldmatrix.sync.aligned.m8n8.x4.trans.shared.b16 {%0,%1,%2,%3}, [%4];"
                 : "=r"(r[0]), "=r"(r[1]), "=r"(r[2]), "=r"(r[3]) : "r"(a));
}

__device__ __forceinline__ void mma16816(float* c, const uint32_t* a, const uint32_t* b)
{
    asm volatile("mma.sync.aligned.m16n8k16.row.col.f32.bf16.bf16.f32 "
                 "{%0,%1,%2,%3}, {%4,%5,%6,%7}, {%8,%9}, {%0,%1,%2,%3};"
                 : "+f"(c[0]), "+f"(c[1]), "+f"(c[2]), "+f"(c[3])
                 : "r"(a[0]), "r"(a[1]), "r"(a[2]), "r"(a[3]),
                   "r"(b[0]), "r"(b[1]));
}

// --------- tensor-core GEMM: C[M,256] = gather(A)[M,Kd] @ W[Kd,256] ---------
// bf16x3-split emulation of fp32. Block tile 128x64, 8 warps, warp tile 32x32.
// optional dual-write: C2[row,col] = qv[row>>4,col] - kall[knn[row],col] + C[row,col]
#define ASTR 40   /* As row stride in bf16 (32 + 8 pad) */
#define BSTR 72   /* Bs row stride in bf16 (64 + 8 pad) */

__global__ __launch_bounds__(256, 2) void tgemm(
    const float* __restrict__ A, const int* __restrict__ rowmap,
    const float* __restrict__ W, const float* __restrict__ bias,
    float* __restrict__ C, int Kd, int relu,
    const float* __restrict__ qv, const float* __restrict__ kall,
    const int* __restrict__ knn, float* __restrict__ C2)
{
    __shared__ __nv_bfloat16 As[2][128][ASTR];   // [hi/lo][m][k]
    __shared__ __nv_bfloat16 Bs[2][32][BSTR];    // [hi/lo][k][n]
    __shared__ int rmap[128];

    const int tid = threadIdx.x;
    const int m0  = blockIdx.y * 128;
    const int n0  = blockIdx.x * 64;

    if (tid < 128) rmap[tid] = rowmap ? rowmap[m0 + tid] : (m0 + tid);
    __syncthreads();

    // ---- load-slot mapping ----
    const int arow = tid >> 1;               // 0..127
    const int akk  = (tid & 1) * 16;         // 0 or 16
    const float* aRow = A + (size_t)rmap[arow] * Kd + akk;

    const int bkr = tid >> 3;                // 0..31
    const int bnc = (tid & 7) * 8;           // 0..56
    const float* bRow = W + (size_t)bkr * COUT + n0 + bnc;

    // ---- warp tiling ----
    const int lane = tid & 31;
    const int wm = (tid >> 5) >> 1;          // 0..3
    const int wn = (tid >> 5) & 1;           // 0..1
    const int aFrow = wm * 32 + (lane & 15); // frag row
    const int aFk   = (lane >> 4) * 8;       // 0/8
    const int bFk   = (lane & 7) + ((lane >> 3) & 1) * 8;  // 0..15
    const int bFn   = (lane >> 4) * 8;       // 0/8

    float acc[2][4][4];
#pragma unroll
    for (int i = 0; i < 2; i++)
#pragma unroll
        for (int j = 0; j < 4; j++)
#pragma unroll
            for (int l = 0; l < 4; l++) acc[i][j][l] = 0.0f;

    const int nk = Kd >> 5;

    // prologue prefetch (chunk 0)
    float4 a4[4], b4[2];
#pragma unroll
    for (int j = 0; j < 4; j++) a4[j] = *(const float4*)(aRow + j*4);
    b4[0] = *(const float4*)(bRow);
    b4[1] = *(const float4*)(bRow + 4);

    for (int t = 0; t < nk; t++) {
        // ---- convert + store smem ----
#pragma unroll
        for (int j = 0; j < 4; j++) {
            uint32_t h0, l0, h1, l1;
            split2(a4[j].x, a4[j].y, h0, l0);
            split2(a4[j].z, a4[j].w, h1, l1);
            *(uint32_t*)&As[0][arow][akk + j*4]     = h0;
            *(uint32_t*)&As[0][arow][akk + j*4 + 2] = h1;
            *(uint32_t*)&As[1][arow][akk + j*4]     = l0;
            *(uint32_t*)&As[1][arow][akk + j*4 + 2] = l1;
        }
#pragma unroll
        for (int j = 0; j < 2; j++) {
            uint32_t h0, l0, h1, l1;
            split2(b4[j].x, b4[j].y, h0, l0);
            split2(b4[j].z, b4[j].w, h1, l1);
            *(uint32_t*)&Bs[0][bkr][bnc + j*4]     = h0;
            *(uint32_t*)&Bs[0][bkr][bnc + j*4 + 2] = h1;
            *(uint32_t*)&Bs[1][bkr][bnc + j*4]     = l0;
            *(uint32_t*)&Bs[1][bkr][bnc + j*4 + 2] = l1;
        }
        __syncthreads();

        // ---- prefetch next chunk ----
        if (t + 1 < nk) {
            const float* ap = aRow + (size_t)(t+1) * 32;
            const float* bp = bRow + (size_t)(t+1) * 32 * COUT;
#pragma unroll
            for (int j = 0; j < 4; j++) a4[j] = *(const float4*)(ap + j*4);
            b4[0] = *(const float4*)(bp);
            b4[1] = *(const float4*)(bp + 4);
        }

        // ---- compute: two k16 sub-steps ----
#pragma unroll
        for (int s = 0; s < 2; s++) {
            const int sk = s * 16;
            uint32_t ah[2][4], al[2][4], bh[4][2], bl[4][2];
#pragma unroll
            for (int mt = 0; mt < 2; mt++) {
                ldsm_x4(ah[mt], &As[0][aFrow + mt*16][sk + aFk]);
                ldsm_x4(al[mt], &As[1][aFrow + mt*16][sk + aFk]);
            }
#pragma unroll
            for (int g = 0; g < 2; g++) {
                uint32_t tmp[4];
                ldsm_x4_t(tmp, &Bs[0][sk + bFk][wn*32 + g*16 + bFn]);
                bh[g*2][0]   = tmp[0]; bh[g*2][1]   = tmp[1];
                bh[g*2+1][0] = tmp[2]; bh[g*2+1][1] = tmp[3];
                ldsm_x4_t(tmp, &Bs[1][sk + bFk][wn*32 + g*16 + bFn]);
                bl[g*2][0]   = tmp[0]; bl[g*2][1]   = tmp[1];
                bl[g*2+1][0] = tmp[2]; bl[g*2+1][1] = tmp[3];
            }
#pragma unroll
            for (int mt = 0; mt < 2; mt++)
#pragma unroll
                for (int nt = 0; nt < 4; nt++) {
                    mma16816(acc[mt][nt], ah[mt], bh[nt]);
                    mma16816(acc[mt][nt], al[mt], bh[nt]);
                    mma16816(acc[mt][nt], ah[mt], bl[nt]);
                }
        }
        __syncthreads();
    }

    // ---- epilogue ----
    const int quad = lane >> 2, tq = lane & 3;
#pragma unroll
    for (int mt = 0; mt < 2; mt++) {
        int r0 = m0 + wm*32 + mt*16 + quad;
        int r1 = r0 + 8;
        const float *q0 = nullptr, *k0p = nullptr, *q1 = nullptr, *k1p = nullptr;
        if (C2) {
            q0 = qv + (size_t)(r0 >> 4) * COUT;  k0p = kall + (size_t)knn[r0] * COUT;
            q1 = qv + (size_t)(r1 >> 4) * COUT;  k1p = kall + (size_t)knn[r1] * COUT;
        }
#pragma unroll
        for (int nt = 0; nt < 4; nt++) {
            int col = n0 + wn*32 + nt*8 + tq*2;
            float o0 = acc[mt][nt][0], o1 = acc[mt][nt][1];
            float o2 = acc[mt][nt][2], o3 = acc[mt][nt][3];
            if (bias) { float bb0 = bias[col], bb1 = bias[col+1];
                        o0 += bb0; o1 += bb1; o2 += bb0; o3 += bb1; }
            if (relu) { o0 = fmaxf(o0,0.f); o1 = fmaxf(o1,0.f);
                        o2 = fmaxf(o2,0.f); o3 = fmaxf(o3,0.f); }
            float2 v0 = make_float2(o0, o1);
            float2 v1 = make_float2(o2, o3);
            *(float2*)(C + (size_t)r0*COUT + col) = v0;
            *(float2*)(C + (size_t)r1*COUT + col) = v1;
            if (C2) {
                float2 w0, w1;
                w0.x = __fadd_rn(__fsub_rn(q0[col],   k0p[col]),   o0);
                w0.y = __fadd_rn(__fsub_rn(q0[col+1], k0p[col+1]), o1);
                w1.x = __fadd_rn(__fsub_rn(q1[col],   k1p[col]),   o2);
                w1.y = __fadd_rn(__fsub_rn(q1[col+1], k1p[col+1]), o3);
                *(float2*)(C2 + (size_t)r0*COUT + col) = w0;
                *(float2*)(C2 + (size_t)r1*COUT + col) = w1;
            }
        }
    }
}

// ------------------ pos-enc layer 1 (3 -> 256, relu) -----------------------
__global__ void h1_kernel(const float* __restrict__ xyz, const float* __restrict__ newxyz,
                          const float* __restrict__ dw1, const float* __restrict__ db1)
{
    int r = blockIdx.x;
    int c = threadIdx.x;
    int g  = g_knn[r];
    int bs = r >> 4;
    float cx = xyz[(size_t)g*3+0] - newxyz[(size_t)bs*3+0];
    float cy = xyz[(size_t)g*3+1] - newxyz[(size_t)bs*3+1];
    float cz = xyz[(size_t)g*3+2] - newxyz[(size_t)bs*3+2];
    float h = db1[c];
    h = fmaf(cx, dw1[0*COUT + c], h);
    h = fmaf(cy, dw1[1*COUT + c], h);
    h = fmaf(cz, dw1[2*COUT + c], h);
    g_bufB[(size_t)r*COUT + c] = fmaxf(h, 0.0f);
}

// --------------- softmax over K axis + weighted sum (v gathered) -----------
__global__ __launch_bounds__(256) void softmax_reduce_kernel()
{
    int bs = blockIdx.x;
    int c  = threadIdx.x;
    __shared__ int kn[16];
    if (c < 16) kn[c] = g_knn[bs*16 + c];
    __syncthreads();

    size_t base = (size_t)bs * KNBR * COUT + c;
    float a[16];
    float mx = -3.4e38f;
#pragma unroll
    for (int i = 0; i < 16; i++) {
        a[i] = g_bufA[base + (size_t)i*COUT] * 0.0625f;
        mx = fmaxf(mx, a[i]);
    }
    float se = 0.0f;
#pragma unroll
    for (int i = 0; i < 16; i++) { a[i] = expf(a[i] - mx); se += a[i]; }
    float inv = 1.0f / se;
    float acc = 0.0f;
#pragma unroll
    for (int i = 0; i < 16; i++) {
        float vp = g_vall[(size_t)kn[i]*COUT + c] + g_pos[base + (size_t)i*COUT];
        acc = fmaf(a[i]*inv, vp, acc);
    }
    g_res0[(size_t)bs*COUT + c] = acc;
}

// ---------------------------- BatchNorm ------------------------------------
__global__ void bn_partial_kernel()
{
    int blk = blockIdx.x;
    int c   = threadIdx.x;
    float s = 0.0f, q = 0.0f;
    for (int r = blk*128; r < blk*128 + 128; r++) {
        float x = g_res1[(size_t)r*COUT + c];
        s += x; q = fmaf(x, x, q);
    }
    g_psum[blk*COUT + c] = s;
    g_psq [blk*COUT + c] = q;
}

__global__ void bn_final_kernel(const float* __restrict__ bng, const float* __restrict__ bnb)
{
    int c = threadIdx.x;
    float s = 0.0f, q = 0.0f;
    for (int i = 0; i < 64; i++) { s += g_psum[i*COUT + c]; q += g_psq[i*COUT + c]; }
    float mean = s * (1.0f/(float)BSR);
    float var  = fmaxf(q * (1.0f/(float)BSR) - mean*mean, 0.0f);
    float sc   = bng[c] * rsqrtf(var + 1e-5f);
    g_scale[c] = sc;
    g_shift[c] = bnb[c] - mean * sc;
}

__global__ void bn_apply_kernel(float* __restrict__ out)
{
    size_t e = (size_t)blockIdx.x * blockDim.x + threadIdx.x;
    int c = (int)(e & 255);
    out[e] = fmaxf(fmaf(g_res1[e], g_scale[c], g_shift[c]), 0.0f);
}

// ------------------------------ launch --------------------------------------
extern "C" void kernel_launch(void* const* d_in, const int* in_sizes, int n_in,
                              void* d_out, int out_size)
{
    const float* xyz    = (const float*)d_in[0];
    const float* points = (const float*)d_in[1];
    const float* wq     = (const float*)d_in[2];
    const float* wk     = (const float*)d_in[3];
    const float* wv     = (const float*)d_in[4];
    const float* dw1    = (const float*)d_in[5];
    const float* db1    = (const float*)d_in[6];
    const float* dw2    = (const float*)d_in[7];
    const float* db2    = (const float*)d_in[8];
    const float* gw1    = (const float*)d_in[9];
    const float* gb1    = (const float*)d_in[10];
    const float* gw2    = (const float*)d_in[11];
    const float* gb2    = (const float*)d_in[12];
    const float* lw     = (const float*)d_in[13];
    const float* lb     = (const float*)d_in[14];
    const float* bng    = (const float*)d_in[15];
    const float* bnb    = (const float*)d_in[16];

    float* out     = (float*)d_out;
    float* newxyz  = out;
    float* res_out = out + (size_t)BSR*3;

    void *ppos, *pA, *pB, *pk, *pv, *pq, *pr0, *pr1, *pfps, *pknn;
    cudaGetSymbolAddress(&ppos, g_pos);
    cudaGetSymbolAddress(&pA,   g_bufA);
    cudaGetSymbolAddress(&pB,   g_bufB);
    cudaGetSymbolAddress(&pk,   g_kall);
    cudaGetSymbolAddress(&pv,   g_vall);
    cudaGetSymbolAddress(&pq,   g_q);
    cudaGetSymbolAddress(&pr0,  g_res0);
    cudaGetSymbolAddress(&pr1,  g_res1);
    cudaGetSymbolAddress(&pfps, g_fps);
    cudaGetSymbolAddress(&pknn, g_knn);

    // 1. FPS (+ writes new_xyz)
    fps_kernel<<<BB, 1024>>>(xyz, newxyz);
    // 2. KNN indices
    knn_kernel<<<BSR/8, 256>>>(xyz, newxyz);
    // 3/4. project ALL points once: k_all / v_all  (M=32768, Kd=128)
    tgemm<<<dim3(COUT/64, NPTS/128), 256>>>(points, nullptr, wk, nullptr,
        (float*)pk, CIN, 0, nullptr, nullptr, nullptr, nullptr);
    tgemm<<<dim3(COUT/64, NPTS/128), 256>>>(points, nullptr, wv, nullptr,
        (float*)pv, CIN, 0, nullptr, nullptr, nullptr, nullptr);
    // 5. q = gather(points, fps) @ wq  (M=8192)
    tgemm<<<dim3(COUT/64, BSR/128), 256>>>(points, (const int*)pfps, wq, nullptr,
        (float*)pq, CIN, 0, nullptr, nullptr, nullptr, nullptr);
    // 6. pos-enc layer 1 -> bufB
    h1_kernel<<<MROWS, 256>>>(xyz, newxyz, dw1, db1);
    // 7. pos = h1 @ dw2 + db2 -> g_pos; fused dual-write a1 = q - k_gather + pos -> bufA
    tgemm<<<dim3(COUT/64, MROWS/128), 256>>>((const float*)pB, nullptr, dw2, db2,
        (float*)ppos, COUT, 0,
        (const float*)pq, (const float*)pk, (const int*)pknn, (float*)pA);
    // 8. h2 = relu(a1 @ gw1 + gb1) -> bufB
    tgemm<<<dim3(COUT/64, MROWS/128), 256>>>((const float*)pA, nullptr, gw1, gb1,
        (float*)pB, COUT, 1, nullptr, nullptr, nullptr, nullptr);
    // 9. att = h2 @ gw2 + gb2 -> bufA
    tgemm<<<dim3(COUT/64, MROWS/128), 256>>>((const float*)pB, nullptr, gw2, gb2,
        (float*)pA, COUT, 0, nullptr, nullptr, nullptr, nullptr);
    // 10. softmax over K + weighted sum of (v_gather + pos) -> res0
    softmax_reduce_kernel<<<BSR, 256>>>();
    // 11. res1 = res0 @ lw + lb
    tgemm<<<dim3(COUT/64, BSR/128), 256>>>((const float*)pr0, nullptr, lw, lb,
        (float*)pr1, COUT, 0, nullptr, nullptr, nullptr, nullptr);
    // 12. BatchNorm (training stats) + ReLU -> output
    bn_partial_kernel<<<64, 256>>>();
    bn_final_kernel<<<1, 256>>>(bng, bnb);
    bn_apply_kernel<<<(BSR*COUT)/1024, 1024>>>(res_out);
}

// round 7
// speedup vs baseline: 1.3616x; 1.0427x over previous
#include <cuda_runtime.h>
#include <cuda_bf16.h>
#include <math.h>
#include <stdint.h>

#define BB   8
#define NN   4096
#define SS   1024
#define KNBR 16
#define CIN  128
#define COUT 256
#define MROWS (BB*SS*KNBR)   /* 131072 */
#define BSR   (BB*SS)        /* 8192  */
#define NPTS  (BB*NN)        /* 32768 */

typedef __nv_bfloat16 bf16;

// ---------------- static device scratch (no allocs allowed) ----------------
__device__ float g_pos [(size_t)MROWS*COUT];
__device__ float g_att [(size_t)MROWS*COUT];
__device__ bf16  g_a1h [(size_t)MROWS*COUT];
__device__ bf16  g_a1l [(size_t)MROWS*COUT];
__device__ bf16  g_x1h [(size_t)MROWS*COUT];   // h1 then h2
__device__ bf16  g_x1l [(size_t)MROWS*COUT];
__device__ bf16  g_ph  [(size_t)NPTS*CIN];
__device__ bf16  g_pl  [(size_t)NPTS*CIN];
__device__ float g_kall[(size_t)NPTS*COUT];
__device__ float g_vall[(size_t)NPTS*COUT];
__device__ float g_q   [(size_t)BSR*COUT];
__device__ bf16  g_r0h [(size_t)BSR*COUT];
__device__ bf16  g_r0l [(size_t)BSR*COUT];
__device__ float g_res1[(size_t)BSR*COUT];
__device__ int   g_fps [BSR];
__device__ int   g_knn [MROWS];
__device__ float g_psum[64*COUT];
__device__ float g_psq [64*COUT];
__device__ float g_scale[COUT];
__device__ float g_shift[COUT];
// pre-split weights
__device__ bf16  g_wkh[CIN*COUT],  g_wkl[CIN*COUT];
__device__ bf16  g_wvh[CIN*COUT],  g_wvl[CIN*COUT];
__device__ bf16  g_wqh[CIN*COUT],  g_wql[CIN*COUT];
__device__ bf16  g_dw2h[COUT*COUT], g_dw2l[COUT*COUT];
__device__ bf16  g_gw1h[COUT*COUT], g_gw1l[COUT*COUT];
__device__ bf16  g_gw2h[COUT*COUT], g_gw2l[COUT*COUT];
__device__ bf16  g_lwh[COUT*COUT],  g_lwl[COUT*COUT];

// -------------------- bf16 split helper ------------------------------------
__device__ __forceinline__ void split2(float x0, float x1, uint32_t& hi, uint32_t& lo)
{
    bf16 h0 = __float2bfloat16(x0);
    bf16 h1 = __float2bfloat16(x1);
    float r0 = __fsub_rn(x0, __bfloat162float(h0));
    float r1 = __fsub_rn(x1, __bfloat162float(h1));
    bf16 l0 = __float2bfloat16(r0);
    bf16 l1 = __float2bfloat16(r1);
    hi = (uint32_t)__bfloat16_as_ushort(h0) | ((uint32_t)__bfloat16_as_ushort(h1) << 16);
    lo = (uint32_t)__bfloat16_as_ushort(l0) | ((uint32_t)__bfloat16_as_ushort(l1) << 16);
}

// ---------------------------- FPS -----------------------------------------
__global__ __launch_bounds__(1024) void fps_kernel(const float* __restrict__ xyz,
                                                   float* __restrict__ newxyz)
{
    int b   = blockIdx.x;
    int tid = threadIdx.x;
    const float* base = xyz + (size_t)b * NN * 3;

    float px[4], py[4], pz[4], dist[4];
#pragma unroll
    for (int j = 0; j < 4; j++) {
        int i = tid * 4 + j;
        px[j] = base[i*3+0]; py[j] = base[i*3+1]; pz[j] = base[i*3+2];
        dist[j] = 1e10f;
    }

    __shared__ float swv[32];
    __shared__ int   swi[32];
    __shared__ int   sfar;

    int far  = 0;
    int lane = tid & 31, wid = tid >> 5;

    for (int s = 0; s < SS; s++) {
        float cx = __ldg(base + far*3 + 0);
        float cy = __ldg(base + far*3 + 1);
        float cz = __ldg(base + far*3 + 2);
        if (tid == 0) {
            g_fps[b*SS + s] = b*NN + far;
            newxyz[((size_t)b*SS + s)*3 + 0] = cx;
            newxyz[((size_t)b*SS + s)*3 + 1] = cy;
            newxyz[((size_t)b*SS + s)*3 + 2] = cz;
        }
        float bv = -1.0f; int bi = 0;
#pragma unroll
        for (int j = 0; j < 4; j++) {
            float dx = __fsub_rn(px[j], cx);
            float dy = __fsub_rn(py[j], cy);
            float dz = __fsub_rn(pz[j], cz);
            float d  = __fadd_rn(__fadd_rn(__fmul_rn(dx,dx), __fmul_rn(dy,dy)),
                                 __fmul_rn(dz,dz));
            dist[j] = fminf(dist[j], d);
            if (dist[j] > bv) { bv = dist[j]; bi = tid*4 + j; }
        }
#pragma unroll
        for (int off = 16; off; off >>= 1) {
            float ov = __shfl_xor_sync(0xffffffffu, bv, off);
            int   oi = __shfl_xor_sync(0xffffffffu, bi, off);
            if (ov > bv || (ov == bv && oi < bi)) { bv = ov; bi = oi; }
        }
        if (lane == 0) { swv[wid] = bv; swi[wid] = bi; }
        __syncthreads();
        if (tid < 32) {
            bv = swv[tid]; bi = swi[tid];
#pragma unroll
            for (int off = 16; off; off >>= 1) {
                float ov = __shfl_xor_sync(0xffffffffu, bv, off);
                int   oi = __shfl_xor_sync(0xffffffffu, bi, off);
                if (ov > bv || (ov == bv && oi < bi)) { bv = ov; bi = oi; }
            }
            if (tid == 0) sfar = bi;
        }
        __syncthreads();
        far = sfar;
    }
}

// ---------------------------- KNN -----------------------------------------
__global__ __launch_bounds__(256) void knn_kernel(const float* __restrict__ xyz,
                                                  const float* __restrict__ newxyz)
{
    int warp = (blockIdx.x * blockDim.x + threadIdx.x) >> 5;
    int lane = threadIdx.x & 31;
    int wloc = threadIdx.x >> 5;
    int b = warp / SS;
    const float* base = xyz + (size_t)b * NN * 3;

    float nx = newxyz[(size_t)warp*3+0];
    float ny = newxyz[(size_t)warp*3+1];
    float nz = newxyz[(size_t)warp*3+2];
    float ns = fmaf(nz, nz, fmaf(ny, ny, __fmul_rn(nx, nx)));

    float v[16]; int id[16];
#pragma unroll
    for (int t = 0; t < 16; t++) { v[t] = 3.4e38f; id[t] = 0x7fffffff; }

    for (int j = lane; j < NN; j += 32) {
        float x = base[j*3+0], y = base[j*3+1], z = base[j*3+2];
        float dot = fmaf(z, nz, fmaf(y, ny, __fmul_rn(x, nx)));
        float nq  = fmaf(z, z,  fmaf(y, y,  __fmul_rn(x, x)));
        float d   = __fadd_rn(__fsub_rn(ns, __fmul_rn(2.0f, dot)), nq);
        if (d < v[15]) {
            v[15] = d; id[15] = j;
#pragma unroll
            for (int t = 15; t > 0; t--) {
                if (v[t] < v[t-1] || (v[t] == v[t-1] && id[t] < id[t-1])) {
                    float tv = v[t]; v[t] = v[t-1]; v[t-1] = tv;
                    int   ti = id[t]; id[t] = id[t-1]; id[t-1] = ti;
                } else break;
            }
        }
    }

    __shared__ float smd[8][512];
    __shared__ int   smi[8][512];
#pragma unroll
    for (int t = 0; t < 16; t++) {
        smd[wloc][lane*16 + t] = v[t];
        smi[wloc][lane*16 + t] = id[t];
    }
    __syncwarp();

    int p = 0;
    for (int t = 0; t < 16; t++) {
        float cv = (p < 16) ? smd[wloc][lane*16 + p] : 3.4e38f;
        int   ci = (p < 16) ? smi[wloc][lane*16 + p] : 0x7fffffff;
        float mv = cv; int mi = ci;
#pragma unroll
        for (int off = 16; off; off >>= 1) {
            float ov = __shfl_xor_sync(0xffffffffu, mv, off);
            int   oi = __shfl_xor_sync(0xffffffffu, mi, off);
            if (ov < mv || (ov == mv && oi < mi)) { mv = ov; mi = oi; }
        }
        if (cv == mv && ci == mi) p++;
        if (lane == 0) g_knn[(size_t)warp*16 + t] = b*NN + mi;
        __syncwarp();
    }
}

// -------------------- fp32 -> bf16 hi/lo conversion -------------------------
__global__ void cvt_kernel(const float* __restrict__ src,
                           bf16* __restrict__ hi, bf16* __restrict__ lo, int n)
{
    int e = (blockIdx.x * blockDim.x + threadIdx.x) * 2;
    if (e >= n) return;
    uint32_t h, l;
    split2(src[e], src[e+1], h, l);
    *(uint32_t*)&hi[e] = h;
    *(uint32_t*)&lo[e] = l;
}

// ------------------------- mma helpers --------------------------------------
__device__ __forceinline__ void cp16(void* s, const void* g)
{
    unsigned sa = (unsigned)__cvta_generic_to_shared(s);
    asm volatile("cp.async.ca.shared.global [%0], [%1], 16;\n" :: "r"(sa), "l"(g));
}
#define CP_COMMIT() asm volatile("cp.async.commit_group;\n")

__device__ __forceinline__ void ldsm_x4(uint32_t* r, const void* p)
{
    uint32_t a = (uint32_t)__cvta_generic_to_shared(p);
    asm volatile("ldmatrix.sync.aligned.m8n8.x4.shared.b16 {%0,%1,%2,%3}, [%4];"
                 : "=r"(r[0]), "=r"(r[1]), "=r"(r[2]), "=r"(r[3]) : "r"(a));
}

__device__ __forceinline__ void ldsm_x4_t(uint32_t* r, const void* p)
{
    uint32_t a = (uint32_t)__cvta_generic_to_shared(p);
    asm volatile("ldmatrix.sync.aligned.m8n8.x4.trans.shared.b16 {%0,%1,%2,%3}, [%4];"
                 : "=r"(r[0]), "=r"(r[1]), "=r"(r[2]), "=r"(r[3]) : "r"(a));
}

__device__ __forceinline__ void mma16816(float* c, const uint32_t* a, const uint32_t* b)
{
    asm volatile("mma.sync.aligned.m16n8k16.row.col.f32.bf16.bf16.f32 "
                 "{%0,%1,%2,%3}, {%4,%5,%6,%7}, {%8,%9}, {%0,%1,%2,%3};"
                 : "+f"(c[0]), "+f"(c[1]), "+f"(c[2]), "+f"(c[3])
                 : "r"(a[0]), "r"(a[1]), "r"(a[2]), "r"(a[3]),
                   "r"(b[0]), "r"(b[1]));
}

// --------- pre-split bf16 tensor-core GEMM: C[M,256] = A[M,Kd] @ W[Kd,256] ---
// A,W given as hi/lo bf16 planes (3-term fp32 emulation).
// outputs (any may be null): C fp32; (Chi,Clo) bf16 split (after bias/relu);
// dual mode (qv,kall,knn,A1hi,A1lo): a1 = qv[row>>4] - kall[knn[row]] + val,
// a1 stored split.
#define KCH   16
#define ASTR2 24   /* 16 + 8 pad bf16 -> 48B rows, 16B aligned */
#define BSTR2 72   /* 64 + 8 pad bf16 -> 144B rows */

__global__ __launch_bounds__(256, 2) void tgemm_bf(
    const bf16* __restrict__ Ahi, const bf16* __restrict__ Alo,
    const int* __restrict__ rowmap,
    const bf16* __restrict__ Whi, const bf16* __restrict__ Wlo,
    const float* __restrict__ bias, int Kd, int relu,
    float* __restrict__ C, bf16* __restrict__ Chi, bf16* __restrict__ Clo,
    const float* __restrict__ qv, const float* __restrict__ kall,
    const int* __restrict__ knn,
    bf16* __restrict__ A1hi, bf16* __restrict__ A1lo)
{
    __shared__ bf16 As[2][2][128][ASTR2];
    __shared__ bf16 Bs[2][2][KCH][BSTR2];
    __shared__ int rmap[128];

    const int tid = threadIdx.x;
    const int m0  = blockIdx.y * 128;
    const int n0  = blockIdx.x * 64;

    if (tid < 128) rmap[tid] = rowmap ? rowmap[m0 + tid] : (m0 + tid);
    __syncthreads();

    // A load: thread -> row (tid>>1), 8-bf16 chunk (tid&1), both planes
    const int arow = tid >> 1;
    const int ach  = (tid & 1) * 8;
    const bf16* aSrcH = Ahi + (size_t)rmap[arow] * Kd + ach;
    const bf16* aSrcL = Alo + (size_t)rmap[arow] * Kd + ach;

    // B load: thread -> plane (tid>>7), k row ((tid>>3)&15), 8-bf16 chunk (tid&7)
    const int bpl = tid >> 7;
    const int bk  = (tid >> 3) & 15;
    const int bch = (tid & 7) * 8;
    const bf16* bSrc = (bpl ? Wlo : Whi) + (size_t)bk * COUT + n0 + bch;

    // warp tiling: 8 warps, warp tile 32x32
    const int lane = tid & 31;
    const int wm = (tid >> 5) >> 1;
    const int wn = (tid >> 5) & 1;
    const int aFrow = wm * 32 + (lane & 15);
    const int aFk   = (lane >> 4) * 8;
    const int bFk   = (lane & 7) + ((lane >> 3) & 1) * 8;
    const int bFn   = (lane >> 4) * 8;

    float acc[2][4][4];
#pragma unroll
    for (int i = 0; i < 2; i++)
#pragma unroll
        for (int j = 0; j < 4; j++)
#pragma unroll
            for (int l = 0; l < 4; l++) acc[i][j][l] = 0.0f;

    const int nk = Kd >> 4;

    // prologue: stage 0
    {
        cp16(&As[0][0][arow][ach], aSrcH);
        cp16(&As[0][1][arow][ach], aSrcL);
        cp16(&Bs[0][bpl][bk][bch], bSrc);
        CP_COMMIT();
    }

    for (int t = 0; t < nk; t++) {
        const int cur = t & 1;
        if (t + 1 < nk) {
            const int nb = (t + 1) & 1;
            const int k0 = (t + 1) * KCH;
            cp16(&As[nb][0][arow][ach], aSrcH + k0);
            cp16(&As[nb][1][arow][ach], aSrcL + k0);
            cp16(&Bs[nb][bpl][bk][bch], bSrc + (size_t)k0 * COUT);
            CP_COMMIT();
            asm volatile("cp.async.wait_group 1;\n" ::: "memory");
        } else {
            asm volatile("cp.async.wait_group 0;\n" ::: "memory");
        }
        __syncthreads();

        uint32_t ah[2][4], al[2][4], bh[4][2], bl[4][2];
#pragma unroll
        for (int mt = 0; mt < 2; mt++) {
            ldsm_x4(ah[mt], &As[cur][0][aFrow + mt*16][aFk]);
            ldsm_x4(al[mt], &As[cur][1][aFrow + mt*16][aFk]);
        }
#pragma unroll
        for (int g = 0; g < 2; g++) {
            uint32_t tmp[4];
            ldsm_x4_t(tmp, &Bs[cur][0][bFk][wn*32 + g*16 + bFn]);
            bh[g*2][0]   = tmp[0]; bh[g*2][1]   = tmp[1];
            bh[g*2+1][0] = tmp[2]; bh[g*2+1][1] = tmp[3];
            ldsm_x4_t(tmp, &Bs[cur][1][bFk][wn*32 + g*16 + bFn]);
            bl[g*2][0]   = tmp[0]; bl[g*2][1]   = tmp[1];
            bl[g*2+1][0] = tmp[2]; bl[g*2+1][1] = tmp[3];
        }
#pragma unroll
        for (int mt = 0; mt < 2; mt++)
#pragma unroll
            for (int nt = 0; nt < 4; nt++) {
                mma16816(acc[mt][nt], ah[mt], bh[nt]);
                mma16816(acc[mt][nt], al[mt], bh[nt]);
                mma16816(acc[mt][nt], ah[mt], bl[nt]);
            }
        __syncthreads();
    }

    // ---- epilogue ----
    const int quad = lane >> 2, tq = lane & 3;
#pragma unroll
    for (int mt = 0; mt < 2; mt++) {
        int r0 = m0 + wm*32 + mt*16 + quad;
        int r1 = r0 + 8;
        const float *q0 = nullptr, *k0p = nullptr, *q1 = nullptr, *k1p = nullptr;
        if (A1hi) {
            q0 = qv + (size_t)(r0 >> 4) * COUT;  k0p = kall + (size_t)knn[r0] * COUT;
            q1 = qv + (size_t)(r1 >> 4) * COUT;  k1p = kall + (size_t)knn[r1] * COUT;
        }
#pragma unroll
        for (int nt = 0; nt < 4; nt++) {
            int col = n0 + wn*32 + nt*8 + tq*2;
            float o0 = acc[mt][nt][0], o1 = acc[mt][nt][1];
            float o2 = acc[mt][nt][2], o3 = acc[mt][nt][3];
            if (bias) { float bb0 = bias[col], bb1 = bias[col+1];
                        o0 += bb0; o1 += bb1; o2 += bb0; o3 += bb1; }
            if (relu) { o0 = fmaxf(o0,0.f); o1 = fmaxf(o1,0.f);
                        o2 = fmaxf(o2,0.f); o3 = fmaxf(o3,0.f); }
            if (C) {
                *(float2*)(C + (size_t)r0*COUT + col) = make_float2(o0, o1);
                *(float2*)(C + (size_t)r1*COUT + col) = make_float2(o2, o3);
            }
            if (Chi) {
                uint32_t h, l;
                split2(o0, o1, h, l);
                *(uint32_t*)&Chi[(size_t)r0*COUT + col] = h;
                *(uint32_t*)&Clo[(size_t)r0*COUT + col] = l;
                split2(o2, o3, h, l);
                *(uint32_t*)&Chi[(size_t)r1*COUT + col] = h;
                *(uint32_t*)&Clo[(size_t)r1*COUT + col] = l;
            }
            if (A1hi) {
                float w0 = __fadd_rn(__fsub_rn(q0[col],   k0p[col]),   o0);
                float w1 = __fadd_rn(__fsub_rn(q0[col+1], k0p[col+1]), o1);
                float w2 = __fadd_rn(__fsub_rn(q1[col],   k1p[col]),   o2);
                float w3 = __fadd_rn(__fsub_rn(q1[col+1], k1p[col+1]), o3);
                uint32_t h, l;
                split2(w0, w1, h, l);
                *(uint32_t*)&A1hi[(size_t)r0*COUT + col] = h;
                *(uint32_t*)&A1lo[(size_t)r0*COUT + col] = l;
                split2(w2, w3, h, l);
                *(uint32_t*)&A1hi[(size_t)r1*COUT + col] = h;
                *(uint32_t*)&A1lo[(size_t)r1*COUT + col] = l;
            }
        }
    }
}

// ------------------ pos-enc layer 1 (3 -> 256, relu, bf16 split out) --------
__global__ void h1_kernel(const float* __restrict__ xyz, const float* __restrict__ newxyz,
                          const float* __restrict__ dw1, const float* __restrict__ db1)
{
    int r = blockIdx.x;          // 0..MROWS-1
    int c = threadIdx.x * 2;     // 0..254
    int g  = g_knn[r];
    int bs = r >> 4;
    float cx = xyz[(size_t)g*3+0] - newxyz[(size_t)bs*3+0];
    float cy = xyz[(size_t)g*3+1] - newxyz[(size_t)bs*3+1];
    float cz = xyz[(size_t)g*3+2] - newxyz[(size_t)bs*3+2];
    float h0 = db1[c],   h1v = db1[c+1];
    h0  = fmaf(cx, dw1[0*COUT + c],   h0);
    h0  = fmaf(cy, dw1[1*COUT + c],   h0);
    h0  = fmaf(cz, dw1[2*COUT + c],   h0);
    h1v = fmaf(cx, dw1[0*COUT + c+1], h1v);
    h1v = fmaf(cy, dw1[1*COUT + c+1], h1v);
    h1v = fmaf(cz, dw1[2*COUT + c+1], h1v);
    h0  = fmaxf(h0, 0.0f);
    h1v = fmaxf(h1v, 0.0f);
    uint32_t h, l;
    split2(h0, h1v, h, l);
    *(uint32_t*)&g_x1h[(size_t)r*COUT + c] = h;
    *(uint32_t*)&g_x1l[(size_t)r*COUT + c] = l;
}

// --------------- softmax over K axis + weighted sum (v gathered) -----------
__global__ __launch_bounds__(128) void softmax_reduce_kernel()
{
    int bs = blockIdx.x;
    int c  = threadIdx.x * 2;
    __shared__ int kn[16];
    if (threadIdx.x < 16) kn[threadIdx.x] = g_knn[bs*16 + threadIdx.x];
    __syncthreads();

    size_t base = (size_t)bs * KNBR * COUT + c;
    float a0[16], a1[16];
    float mx0 = -3.4e38f, mx1 = -3.4e38f;
#pragma unroll
    for (int i = 0; i < 16; i++) {
        a0[i] = g_att[base + (size_t)i*COUT]     * 0.0625f;
        a1[i] = g_att[base + (size_t)i*COUT + 1] * 0.0625f;
        mx0 = fmaxf(mx0, a0[i]);
        mx1 = fmaxf(mx1, a1[i]);
    }
    float s0 = 0.0f, s1 = 0.0f;
#pragma unroll
    for (int i = 0; i < 16; i++) {
        a0[i] = expf(a0[i] - mx0); s0 += a0[i];
        a1[i] = expf(a1[i] - mx1); s1 += a1[i];
    }
    float i0 = 1.0f / s0, i1 = 1.0f / s1;
    float acc0 = 0.0f, acc1 = 0.0f;
#pragma unroll
    for (int i = 0; i < 16; i++) {
        size_t vb = (size_t)kn[i]*COUT + c;
        float vp0 = g_vall[vb]     + g_pos[base + (size_t)i*COUT];
        float vp1 = g_vall[vb + 1] + g_pos[base + (size_t)i*COUT + 1];
        acc0 = fmaf(a0[i]*i0, vp0, acc0);
        acc1 = fmaf(a1[i]*i1, vp1, acc1);
    }
    uint32_t h, l;
    split2(acc0, acc1, h, l);
    *(uint32_t*)&g_r0h[(size_t)bs*COUT + c] = h;
    *(uint32_t*)&g_r0l[(size_t)bs*COUT + c] = l;
}

// ---------------------------- BatchNorm ------------------------------------
__global__ void bn_partial_kernel()
{
    int blk = blockIdx.x;
    int c   = threadIdx.x;
    float s = 0.0f, q = 0.0f;
    for (int r = blk*128; r < blk*128 + 128; r++) {
        float x = g_res1[(size_t)r*COUT + c];
        s += x; q = fmaf(x, x, q);
    }
    g_psum[blk*COUT + c] = s;
    g_psq [blk*COUT + c] = q;
}

__global__ void bn_final_kernel(const float* __restrict__ bng, const float* __restrict__ bnb)
{
    int c = threadIdx.x;
    float s = 0.0f, q = 0.0f;
    for (int i = 0; i < 64; i++) { s += g_psum[i*COUT + c]; q += g_psq[i*COUT + c]; }
    float mean = s * (1.0f/(float)BSR);
    float var  = fmaxf(q * (1.0f/(float)BSR) - mean*mean, 0.0f);
    float sc   = bng[c] * rsqrtf(var + 1e-5f);
    g_scale[c] = sc;
    g_shift[c] = bnb[c] - mean * sc;
}

__global__ void bn_apply_kernel(float* __restrict__ out)
{
    size_t e = (size_t)blockIdx.x * blockDim.x + threadIdx.x;
    int c = (int)(e & 255);
    out[e] = fmaxf(fmaf(g_res1[e], g_scale[c], g_shift[c]), 0.0f);
}

// ------------------------------ launch --------------------------------------
extern "C" void kernel_launch(void* const* d_in, const int* in_sizes, int n_in,
                              void* d_out, int out_size)
{
    const float* xyz    = (const float*)d_in[0];
    const float* points = (const float*)d_in[1];
    const float* wq     = (const float*)d_in[2];
    const float* wk     = (const float*)d_in[3];
    const float* wv     = (const float*)d_in[4];
    const float* dw1    = (const float*)d_in[5];
    const float* db1    = (const float*)d_in[6];
    const float* dw2    = (const float*)d_in[7];
    const float* db2    = (const float*)d_in[8];
    const float* gw1    = (const float*)d_in[9];
    const float* gb1    = (const float*)d_in[10];
    const float* gw2    = (const float*)d_in[11];
    const float* gb2    = (const float*)d_in[12];
    const float* lw     = (const float*)d_in[13];
    const float* lb     = (const float*)d_in[14];
    const float* bng    = (const float*)d_in[15];
    const float* bnb    = (const float*)d_in[16];

    float* out     = (float*)d_out;
    float* newxyz  = out;
    float* res_out = out + (size_t)BSR*3;

#define SYM(p, s) void* p; cudaGetSymbolAddress(&p, s)
    SYM(ppos, g_pos);  SYM(patt, g_att);
    SYM(pa1h, g_a1h);  SYM(pa1l, g_a1l);
    SYM(px1h, g_x1h);  SYM(px1l, g_x1l);
    SYM(pph,  g_ph);   SYM(ppl,  g_pl);
    SYM(pk,   g_kall); SYM(pv,   g_vall);
    SYM(pq,   g_q);
    SYM(pr0h, g_r0h);  SYM(pr0l, g_r0l);
    SYM(pr1,  g_res1);
    SYM(pfps, g_fps);  SYM(pknn, g_knn);
    SYM(pwkh, g_wkh);  SYM(pwkl, g_wkl);
    SYM(pwvh, g_wvh);  SYM(pwvl, g_wvl);
    SYM(pwqh, g_wqh);  SYM(pwql, g_wql);
    SYM(pdw2h, g_dw2h); SYM(pdw2l, g_dw2l);
    SYM(pgw1h, g_gw1h); SYM(pgw1l, g_gw1l);
    SYM(pgw2h, g_gw2h); SYM(pgw2l, g_gw2l);
    SYM(plwh, g_lwh);   SYM(plwl, g_lwl);
#undef SYM

    // 0. pre-split weights + points to bf16 hi/lo
    cvt_kernel<<<(NPTS*CIN)/512, 256>>>(points, (bf16*)pph, (bf16*)ppl, NPTS*CIN);
    cvt_kernel<<<(CIN*COUT)/512, 256>>>(wk,  (bf16*)pwkh,  (bf16*)pwkl,  CIN*COUT);
    cvt_kernel<<<(CIN*COUT)/512, 256>>>(wv,  (bf16*)pwvh,  (bf16*)pwvl,  CIN*COUT);
    cvt_kernel<<<(CIN*COUT)/512, 256>>>(wq,  (bf16*)pwqh,  (bf16*)pwql,  CIN*COUT);
    cvt_kernel<<<(COUT*COUT)/512, 256>>>(dw2, (bf16*)pdw2h, (bf16*)pdw2l, COUT*COUT);
    cvt_kernel<<<(COUT*COUT)/512, 256>>>(gw1, (bf16*)pgw1h, (bf16*)pgw1l, COUT*COUT);
    cvt_kernel<<<(COUT*COUT)/512, 256>>>(gw2, (bf16*)pgw2h, (bf16*)pgw2l, COUT*COUT);
    cvt_kernel<<<(COUT*COUT)/512, 256>>>(lw,  (bf16*)plwh,  (bf16*)plwl,  COUT*COUT);

    // 1. FPS (+ writes new_xyz)
    fps_kernel<<<BB, 1024>>>(xyz, newxyz);
    // 2. KNN indices
    knn_kernel<<<BSR/8, 256>>>(xyz, newxyz);

    // 3/4. k_all / v_all = points @ wk/wv  (M=32768, Kd=128)
    tgemm_bf<<<dim3(COUT/64, NPTS/128), 256>>>(
        (const bf16*)pph, (const bf16*)ppl, nullptr,
        (const bf16*)pwkh, (const bf16*)pwkl, nullptr, CIN, 0,
        (float*)pk, nullptr, nullptr, nullptr, nullptr, nullptr, nullptr, nullptr);
    tgemm_bf<<<dim3(COUT/64, NPTS/128), 256>>>(
        (const bf16*)pph, (const bf16*)ppl, nullptr,
        (const bf16*)pwvh, (const bf16*)pwvl, nullptr, CIN, 0,
        (float*)pv, nullptr, nullptr, nullptr, nullptr, nullptr, nullptr, nullptr);
    // 5. q = gather(points, fps) @ wq  (M=8192)
    tgemm_bf<<<dim3(COUT/64, BSR/128), 256>>>(
        (const bf16*)pph, (const bf16*)ppl, (const int*)pfps,
        (const bf16*)pwqh, (const bf16*)pwql, nullptr, CIN, 0,
        (float*)pq, nullptr, nullptr, nullptr, nullptr, nullptr, nullptr, nullptr);
    // 6. pos-enc layer 1 -> x1 (bf16 split)
    h1_kernel<<<MROWS, 128>>>(xyz, newxyz, dw1, db1);
    // 7. pos = h1 @ dw2 + db2 -> g_pos (fp32);  fused a1 = q - k_gather + pos -> a1 hi/lo
    tgemm_bf<<<dim3(COUT/64, MROWS/128), 256>>>(
        (const bf16*)px1h, (const bf16*)px1l, nullptr,
        (const bf16*)pdw2h, (const bf16*)pdw2l, db2, COUT, 0,
        (float*)ppos, nullptr, nullptr,
        (const float*)pq, (const float*)pk, (const int*)pknn,
        (bf16*)pa1h, (bf16*)pa1l);
    // 8. h2 = relu(a1 @ gw1 + gb1) -> x1 hi/lo (h1 dead)
    tgemm_bf<<<dim3(COUT/64, MROWS/128), 256>>>(
        (const bf16*)pa1h, (const bf16*)pa1l, nullptr,
        (const bf16*)pgw1h, (const bf16*)pgw1l, gb1, COUT, 1,
        nullptr, (bf16*)px1h, (bf16*)px1l, nullptr, nullptr, nullptr, nullptr, nullptr);
    // 9. att = h2 @ gw2 + gb2 -> fp32
    tgemm_bf<<<dim3(COUT/64, MROWS/128), 256>>>(
        (const bf16*)px1h, (const bf16*)px1l, nullptr,
        (const bf16*)pgw2h, (const bf16*)pgw2l, gb2, COUT, 0,
        (float*)patt, nullptr, nullptr, nullptr, nullptr, nullptr, nullptr, nullptr);
    // 10. softmax over K + weighted sum of (v_gather + pos) -> res0 hi/lo
    softmax_reduce_kernel<<<BSR, 128>>>();
    // 11. res1 = res0 @ lw + lb
    tgemm_bf<<<dim3(COUT/64, BSR/128), 256>>>(
        (const bf16*)pr0h, (const bf16*)pr0l, nullptr,
        (const bf16*)plwh, (const bf16*)plwl, lb, COUT, 0,
        (float*)pr1, nullptr, nullptr, nullptr, nullptr, nullptr, nullptr, nullptr);
    // 12. BatchNorm (training stats) + ReLU -> output
    bn_partial_kernel<<<64, 256>>>();
    bn_final_kernel<<<1, 256>>>(bng, bnb);
    bn_apply_kernel<<<(BSR*COUT)/1024, 1024>>>(res_out);
}

// round 8
// speedup vs baseline: 1.6665x; 1.2239x over previous
#include <cuda_runtime.h>
#include <cuda_bf16.h>
#include <math.h>
#include <stdint.h>

#define BB   8
#define NN   4096
#define SS   1024
#define KNBR 16
#define CIN  128
#define COUT 256
#define MROWS (BB*SS*KNBR)   /* 131072 */
#define BSR   (BB*SS)        /* 8192  */
#define NPTS  (BB*NN)        /* 32768 */

typedef __nv_bfloat16 bf16;

// ---------------- static device scratch (no allocs allowed) ----------------
__device__ float g_pos [(size_t)MROWS*COUT];
__device__ float g_att [(size_t)MROWS*COUT];
__device__ bf16  g_a1h [(size_t)MROWS*COUT];
__device__ bf16  g_a1l [(size_t)MROWS*COUT];
__device__ bf16  g_x1h [(size_t)MROWS*COUT];   // h1 then h2
__device__ bf16  g_x1l [(size_t)MROWS*COUT];
__device__ bf16  g_ph  [(size_t)NPTS*CIN];
__device__ bf16  g_pl  [(size_t)NPTS*CIN];
__device__ float g_kall[(size_t)NPTS*COUT];
__device__ float g_vall[(size_t)NPTS*COUT];
__device__ float g_q   [(size_t)BSR*COUT];
__device__ bf16  g_r0h [(size_t)BSR*COUT];
__device__ bf16  g_r0l [(size_t)BSR*COUT];
__device__ float g_res1[(size_t)BSR*COUT];
__device__ int   g_fps [BSR];
__device__ int   g_knn [MROWS];
__device__ float g_psum[64*COUT];
__device__ float g_psq [64*COUT];
__device__ float g_scale[COUT];
__device__ float g_shift[COUT];
// pre-split weights
__device__ bf16  g_wkh[CIN*COUT],  g_wkl[CIN*COUT];
__device__ bf16  g_wvh[CIN*COUT],  g_wvl[CIN*COUT];
__device__ bf16  g_wqh[CIN*COUT],  g_wql[CIN*COUT];
__device__ bf16  g_dw2h[COUT*COUT], g_dw2l[COUT*COUT];
__device__ bf16  g_gw1h[COUT*COUT], g_gw1l[COUT*COUT];
__device__ bf16  g_gw2h[COUT*COUT], g_gw2l[COUT*COUT];
__device__ bf16  g_lwh[COUT*COUT],  g_lwl[COUT*COUT];

// -------------------- bf16 split helper ------------------------------------
__device__ __forceinline__ void split2(float x0, float x1, uint32_t& hi, uint32_t& lo)
{
    bf16 h0 = __float2bfloat16(x0);
    bf16 h1 = __float2bfloat16(x1);
    float r0 = __fsub_rn(x0, __bfloat162float(h0));
    float r1 = __fsub_rn(x1, __bfloat162float(h1));
    bf16 l0 = __float2bfloat16(r0);
    bf16 l1 = __float2bfloat16(r1);
    hi = (uint32_t)__bfloat16_as_ushort(h0) | ((uint32_t)__bfloat16_as_ushort(h1) << 16);
    lo = (uint32_t)__bfloat16_as_ushort(l0) | ((uint32_t)__bfloat16_as_ushort(l1) << 16);
}

// ---------------------------- FPS -----------------------------------------
// 256 threads, 16 pts/thread in regs, xyz staged in smem, 1 barrier/iter.
__global__ __launch_bounds__(256) void fps_kernel(const float* __restrict__ xyz,
                                                  float* __restrict__ newxyz)
{
    __shared__ float sx[NN], sy[NN], sz[NN];
    __shared__ unsigned long long swk[2][8];

    int b   = blockIdx.x;
    int tid = threadIdx.x;
    int lane = tid & 31, wid = tid >> 5;
    const float* base = xyz + (size_t)b * NN * 3;

    for (int i = tid; i < NN; i += 256) {
        sx[i] = base[i*3+0];
        sy[i] = base[i*3+1];
        sz[i] = base[i*3+2];
    }
    __syncthreads();

    float px[16], py[16], pz[16], dist[16];
#pragma unroll
    for (int j = 0; j < 16; j++) {
        int i = tid * 16 + j;
        px[j] = sx[i]; py[j] = sy[i]; pz[j] = sz[i];
        dist[j] = 1e10f;
    }

    int far = 0;
    for (int s = 0; s < SS; s++) {
        float cx = sx[far], cy = sy[far], cz = sz[far];
        if (tid == 0) {
            g_fps[b*SS + s] = b*NN + far;
            newxyz[((size_t)b*SS + s)*3 + 0] = cx;
            newxyz[((size_t)b*SS + s)*3 + 1] = cy;
            newxyz[((size_t)b*SS + s)*3 + 2] = cz;
        }
        float bv = -1.0f; int bi = 0;
#pragma unroll
        for (int j = 0; j < 16; j++) {
            float dx = __fsub_rn(px[j], cx);
            float dy = __fsub_rn(py[j], cy);
            float dz = __fsub_rn(pz[j], cz);
            float d  = __fadd_rn(__fadd_rn(__fmul_rn(dx,dx), __fmul_rn(dy,dy)),
                                 __fmul_rn(dz,dz));
            dist[j] = fminf(dist[j], d);
            if (dist[j] > bv) { bv = dist[j]; bi = tid*16 + j; }  // lowest idx on tie
        }
        // warp argmax: dist >= 0 so float bits are order-preserving as uint
        unsigned key  = __float_as_uint(bv);
        unsigned wmax = __reduce_max_sync(0xffffffffu, key);
        unsigned ball = __ballot_sync(0xffffffffu, key == wmax);
        int src  = __ffs(ball) - 1;                  // lowest lane = lowest index
        int wbi  = __shfl_sync(0xffffffffu, bi, src);
        if (lane == 0)
            swk[s & 1][wid] = ((unsigned long long)wmax << 32)
                            | (unsigned)(NN - 1 - wbi);   // tie -> smaller idx wins max
        __syncthreads();
        unsigned long long best = swk[s & 1][0];
#pragma unroll
        for (int w = 1; w < 8; w++) {
            unsigned long long c = swk[s & 1][w];
            if (c > best) best = c;
        }
        far = NN - 1 - (int)(best & 0xffffffffu);
    }
}

// ---------------------------- KNN -----------------------------------------
__global__ __launch_bounds__(256) void knn_kernel(const float* __restrict__ xyz,
                                                  const float* __restrict__ newxyz)
{
    int warp = (blockIdx.x * blockDim.x + threadIdx.x) >> 5;
    int lane = threadIdx.x & 31;
    int wloc = threadIdx.x >> 5;
    int b = warp / SS;
    const float* base = xyz + (size_t)b * NN * 3;

    float nx = newxyz[(size_t)warp*3+0];
    float ny = newxyz[(size_t)warp*3+1];
    float nz = newxyz[(size_t)warp*3+2];
    float ns = fmaf(nz, nz, fmaf(ny, ny, __fmul_rn(nx, nx)));

    float v[16]; int id[16];
#pragma unroll
    for (int t = 0; t < 16; t++) { v[t] = 3.4e38f; id[t] = 0x7fffffff; }

    for (int j = lane; j < NN; j += 32) {
        float x = base[j*3+0], y = base[j*3+1], z = base[j*3+2];
        float dot = fmaf(z, nz, fmaf(y, ny, __fmul_rn(x, nx)));
        float nq  = fmaf(z, z,  fmaf(y, y,  __fmul_rn(x, x)));
        float d   = __fadd_rn(__fsub_rn(ns, __fmul_rn(2.0f, dot)), nq);
        if (d < v[15]) {
            v[15] = d; id[15] = j;
#pragma unroll
            for (int t = 15; t > 0; t--) {
                if (v[t] < v[t-1] || (v[t] == v[t-1] && id[t] < id[t-1])) {
                    float tv = v[t]; v[t] = v[t-1]; v[t-1] = tv;
                    int   ti = id[t]; id[t] = id[t-1]; id[t-1] = ti;
                } else break;
            }
        }
    }

    __shared__ float smd[8][512];
    __shared__ int   smi[8][512];
#pragma unroll
    for (int t = 0; t < 16; t++) {
        smd[wloc][lane*16 + t] = v[t];
        smi[wloc][lane*16 + t] = id[t];
    }
    __syncwarp();

    int p = 0;
    for (int t = 0; t < 16; t++) {
        float cv = (p < 16) ? smd[wloc][lane*16 + p] : 3.4e38f;
        int   ci = (p < 16) ? smi[wloc][lane*16 + p] : 0x7fffffff;
        float mv = cv; int mi = ci;
#pragma unroll
        for (int off = 16; off; off >>= 1) {
            float ov = __shfl_xor_sync(0xffffffffu, mv, off);
            int   oi = __shfl_xor_sync(0xffffffffu, mi, off);
            if (ov < mv || (ov == mv && oi < mi)) { mv = ov; mi = oi; }
        }
        if (cv == mv && ci == mi) p++;
        if (lane == 0) g_knn[(size_t)warp*16 + t] = b*NN + mi;
        __syncwarp();
    }
}

// -------------------- fp32 -> bf16 hi/lo conversion -------------------------
__global__ void cvt_kernel(const float* __restrict__ src,
                           bf16* __restrict__ hi, bf16* __restrict__ lo, int n)
{
    int e = (blockIdx.x * blockDim.x + threadIdx.x) * 2;
    if (e >= n) return;
    uint32_t h, l;
    split2(src[e], src[e+1], h, l);
    *(uint32_t*)&hi[e] = h;
    *(uint32_t*)&lo[e] = l;
}

// ------------------------- mma helpers --------------------------------------
__device__ __forceinline__ void cp16(void* s, const void* g)
{
    unsigned sa = (unsigned)__cvta_generic_to_shared(s);
    asm volatile("cp.async.ca.shared.global [%0], [%1], 16;\n" :: "r"(sa), "l"(g));
}
#define CP_COMMIT() asm volatile("cp.async.commit_group;\n")

__device__ __forceinline__ void ldsm_x4(uint32_t* r, const void* p)
{
    uint32_t a = (uint32_t)__cvta_generic_to_shared(p);
    asm volatile("ldmatrix.sync.aligned.m8n8.x4.shared.b16 {%0,%1,%2,%3}, [%4];"
                 : "=r"(r[0]), "=r"(r[1]), "=r"(r[2]), "=r"(r[3]) : "r"(a));
}

__device__ __forceinline__ void ldsm_x4_t(uint32_t* r, const void* p)
{
    uint32_t a = (uint32_t)__cvta_generic_to_shared(p);
    asm volatile("ldmatrix.sync.aligned.m8n8.x4.trans.shared.b16 {%0,%1,%2,%3}, [%4];"
                 : "=r"(r[0]), "=r"(r[1]), "=r"(r[2]), "=r"(r[3]) : "r"(a));
}

__device__ __forceinline__ void mma16816(float* c, const uint32_t* a, const uint32_t* b)
{
    asm volatile("mma.sync.aligned.m16n8k16.row.col.f32.bf16.bf16.f32 "
                 "{%0,%1,%2,%3}, {%4,%5,%6,%7}, {%8,%9}, {%0,%1,%2,%3};"
                 : "+f"(c[0]), "+f"(c[1]), "+f"(c[2]), "+f"(c[3])
                 : "r"(a[0]), "r"(a[1]), "r"(a[2]), "r"(a[3]),
                   "r"(b[0]), "r"(b[1]));
}

// --------- pre-split bf16 tensor-core GEMM: C[M,256] = A[M,Kd] @ W[Kd,256] ---
// 4-stage cp.async pipeline, ONE __syncthreads per k16-chunk.
#define KCH    16
#define NSTG   4
#define ASTR2  24   /* 16 + 8 pad bf16 */
#define BSTR2  72   /* 64 + 8 pad bf16 */
#define AS_BYTES  (NSTG*2*128*ASTR2*2)            /* 49152 */
#define BS_BYTES  (NSTG*2*KCH*BSTR2*2)            /* 18432 */
#define TG_SMEM   (AS_BYTES + BS_BYTES + 512)     /* 68096 */

__global__ __launch_bounds__(256, 2) void tgemm_bf(
    const bf16* __restrict__ Ahi, const bf16* __restrict__ Alo,
    const int* __restrict__ rowmap,
    const bf16* __restrict__ Whi, const bf16* __restrict__ Wlo,
    const float* __restrict__ bias, int Kd, int relu,
    float* __restrict__ C, bf16* __restrict__ Chi, bf16* __restrict__ Clo,
    const float* __restrict__ qv, const float* __restrict__ kall,
    const int* __restrict__ knn,
    bf16* __restrict__ A1hi, bf16* __restrict__ A1lo)
{
    extern __shared__ char smraw[];
    typedef bf16 (*AsT)[2][128][ASTR2];
    typedef bf16 (*BsT)[2][KCH][BSTR2];
    AsT As = (AsT)smraw;                        // As[stg][pl][m][k]
    BsT Bs = (BsT)(smraw + AS_BYTES);           // Bs[stg][pl][k][n]
    int* rmap = (int*)(smraw + AS_BYTES + BS_BYTES);

    const int tid = threadIdx.x;
    const int m0  = blockIdx.y * 128;
    const int n0  = blockIdx.x * 64;

    if (tid < 128) rmap[tid] = rowmap ? rowmap[m0 + tid] : (m0 + tid);
    __syncthreads();

    // A load: thread -> row (tid>>1), 8-bf16 chunk (tid&1), both planes
    const int arow = tid >> 1;
    const int ach  = (tid & 1) * 8;
    const bf16* aSrcH = Ahi + (size_t)rmap[arow] * Kd + ach;
    const bf16* aSrcL = Alo + (size_t)rmap[arow] * Kd + ach;

    // B load: thread -> plane (tid>>7), k row ((tid>>3)&15), 8-bf16 chunk (tid&7)
    const int bpl = tid >> 7;
    const int bk  = (tid >> 3) & 15;
    const int bch = (tid & 7) * 8;
    const bf16* bSrc = (bpl ? Wlo : Whi) + (size_t)bk * COUT + n0 + bch;

    // warp tiling: 8 warps, warp tile 32x32
    const int lane = tid & 31;
    const int wm = (tid >> 5) >> 1;
    const int wn = (tid >> 5) & 1;
    const int aFrow = wm * 32 + (lane & 15);
    const int aFk   = (lane >> 4) * 8;
    const int bFk   = (lane & 7) + ((lane >> 3) & 1) * 8;
    const int bFn   = (lane >> 4) * 8;

    float acc[2][4][4];
#pragma unroll
    for (int i = 0; i < 2; i++)
#pragma unroll
        for (int j = 0; j < 4; j++)
#pragma unroll
            for (int l = 0; l < 4; l++) acc[i][j][l] = 0.0f;

    const int nk = Kd >> 4;   // 8 or 16

    // ---- prologue: issue stages 0..2 (one commit group per stage) ----
#pragma unroll
    for (int s = 0; s < NSTG - 1; s++) {
        if (s < nk) {
            int k0 = s * KCH;
            cp16(&As[s][0][arow][ach], aSrcH + k0);
            cp16(&As[s][1][arow][ach], aSrcL + k0);
            cp16(&Bs[s][bpl][bk][bch], bSrc + (size_t)k0 * COUT);
        }
        CP_COMMIT();
    }

    for (int t = 0; t < nk; t++) {
        const int cur = t & (NSTG - 1);
        if (t + NSTG - 1 < nk) {
            asm volatile("cp.async.wait_group 2;\n" ::: "memory");
        } else {
            asm volatile("cp.async.wait_group 0;\n" ::: "memory");
        }
        __syncthreads();

        // issue stage t+3 (slot was last read at iter t-1, protected by the bar)
        if (t + NSTG - 1 < nk) {
            const int stg = (t + NSTG - 1) & (NSTG - 1);
            const int k0  = (t + NSTG - 1) * KCH;
            cp16(&As[stg][0][arow][ach], aSrcH + k0);
            cp16(&As[stg][1][arow][ach], aSrcL + k0);
            cp16(&Bs[stg][bpl][bk][bch], bSrc + (size_t)k0 * COUT);
            CP_COMMIT();
        }

        uint32_t ah[2][4], al[2][4], bh[4][2], bl[4][2];
#pragma unroll
        for (int mt = 0; mt < 2; mt++) {
            ldsm_x4(ah[mt], &As[cur][0][aFrow + mt*16][aFk]);
            ldsm_x4(al[mt], &As[cur][1][aFrow + mt*16][aFk]);
        }
#pragma unroll
        for (int g = 0; g < 2; g++) {
            uint32_t tmp[4];
            ldsm_x4_t(tmp, &Bs[cur][0][bFk][wn*32 + g*16 + bFn]);
            bh[g*2][0]   = tmp[0]; bh[g*2][1]   = tmp[1];
            bh[g*2+1][0] = tmp[2]; bh[g*2+1][1] = tmp[3];
            ldsm_x4_t(tmp, &Bs[cur][1][bFk][wn*32 + g*16 + bFn]);
            bl[g*2][0]   = tmp[0]; bl[g*2][1]   = tmp[1];
            bl[g*2+1][0] = tmp[2]; bl[g*2+1][1] = tmp[3];
        }
#pragma unroll
        for (int mt = 0; mt < 2; mt++)
#pragma unroll
            for (int nt = 0; nt < 4; nt++) {
                mma16816(acc[mt][nt], ah[mt], bh[nt]);
                mma16816(acc[mt][nt], al[mt], bh[nt]);
                mma16816(acc[mt][nt], ah[mt], bl[nt]);
            }
    }

    // ---- epilogue ----
    const int quad = lane >> 2, tq = lane & 3;
#pragma unroll
    for (int mt = 0; mt < 2; mt++) {
        int r0 = m0 + wm*32 + mt*16 + quad;
        int r1 = r0 + 8;
        const float *q0 = nullptr, *k0p = nullptr, *q1 = nullptr, *k1p = nullptr;
        if (A1hi) {
            q0 = qv + (size_t)(r0 >> 4) * COUT;  k0p = kall + (size_t)knn[r0] * COUT;
            q1 = qv + (size_t)(r1 >> 4) * COUT;  k1p = kall + (size_t)knn[r1] * COUT;
        }
#pragma unroll
        for (int nt = 0; nt < 4; nt++) {
            int col = n0 + wn*32 + nt*8 + tq*2;
            float o0 = acc[mt][nt][0], o1 = acc[mt][nt][1];
            float o2 = acc[mt][nt][2], o3 = acc[mt][nt][3];
            if (bias) { float bb0 = bias[col], bb1 = bias[col+1];
                        o0 += bb0; o1 += bb1; o2 += bb0; o3 += bb1; }
            if (relu) { o0 = fmaxf(o0,0.f); o1 = fmaxf(o1,0.f);
                        o2 = fmaxf(o2,0.f); o3 = fmaxf(o3,0.f); }
            if (C) {
                *(float2*)(C + (size_t)r0*COUT + col) = make_float2(o0, o1);
                *(float2*)(C + (size_t)r1*COUT + col) = make_float2(o2, o3);
            }
            if (Chi) {
                uint32_t h, l;
                split2(o0, o1, h, l);
                *(uint32_t*)&Chi[(size_t)r0*COUT + col] = h;
                *(uint32_t*)&Clo[(size_t)r0*COUT + col] = l;
                split2(o2, o3, h, l);
                *(uint32_t*)&Chi[(size_t)r1*COUT + col] = h;
                *(uint32_t*)&Clo[(size_t)r1*COUT + col] = l;
            }
            if (A1hi) {
                float w0 = __fadd_rn(__fsub_rn(q0[col],   k0p[col]),   o0);
                float w1 = __fadd_rn(__fsub_rn(q0[col+1], k0p[col+1]), o1);
                float w2 = __fadd_rn(__fsub_rn(q1[col],   k1p[col]),   o2);
                float w3 = __fadd_rn(__fsub_rn(q1[col+1], k1p[col+1]), o3);
                uint32_t h, l;
                split2(w0, w1, h, l);
                *(uint32_t*)&A1hi[(size_t)r0*COUT + col] = h;
                *(uint32_t*)&A1lo[(size_t)r0*COUT + col] = l;
                split2(w2, w3, h, l);
                *(uint32_t*)&A1hi[(size_t)r1*COUT + col] = h;
                *(uint32_t*)&A1lo[(size_t)r1*COUT + col] = l;
            }
        }
    }
}

// ------------------ pos-enc layer 1 (3 -> 256, relu, bf16 split out) --------
__global__ void h1_kernel(const float* __restrict__ xyz, const float* __restrict__ newxyz,
                          const float* __restrict__ dw1, const float* __restrict__ db1)
{
    int r = blockIdx.x;          // 0..MROWS-1
    int c = threadIdx.x * 2;     // 0..254
    int g  = g_knn[r];
    int bs = r >> 4;
    float cx = xyz[(size_t)g*3+0] - newxyz[(size_t)bs*3+0];
    float cy = xyz[(size_t)g*3+1] - newxyz[(size_t)bs*3+1];
    float cz = xyz[(size_t)g*3+2] - newxyz[(size_t)bs*3+2];
    float h0 = db1[c],   h1v = db1[c+1];
    h0  = fmaf(cx, dw1[0*COUT + c],   h0);
    h0  = fmaf(cy, dw1[1*COUT + c],   h0);
    h0  = fmaf(cz, dw1[2*COUT + c],   h0);
    h1v = fmaf(cx, dw1[0*COUT + c+1], h1v);
    h1v = fmaf(cy, dw1[1*COUT + c+1], h1v);
    h1v = fmaf(cz, dw1[2*COUT + c+1], h1v);
    h0  = fmaxf(h0, 0.0f);
    h1v = fmaxf(h1v, 0.0f);
    uint32_t h, l;
    split2(h0, h1v, h, l);
    *(uint32_t*)&g_x1h[(size_t)r*COUT + c] = h;
    *(uint32_t*)&g_x1l[(size_t)r*COUT + c] = l;
}

// --------------- softmax over K axis + weighted sum (v gathered) -----------
__global__ __launch_bounds__(128) void softmax_reduce_kernel()
{
    int bs = blockIdx.x;
    int c  = threadIdx.x * 2;
    __shared__ int kn[16];
    if (threadIdx.x < 16) kn[threadIdx.x] = g_knn[bs*16 + threadIdx.x];
    __syncthreads();

    size_t base = (size_t)bs * KNBR * COUT + c;
    float a0[16], a1[16];
    float mx0 = -3.4e38f, mx1 = -3.4e38f;
#pragma unroll
    for (int i = 0; i < 16; i++) {
        a0[i] = g_att[base + (size_t)i*COUT]     * 0.0625f;
        a1[i] = g_att[base + (size_t)i*COUT + 1] * 0.0625f;
        mx0 = fmaxf(mx0, a0[i]);
        mx1 = fmaxf(mx1, a1[i]);
    }
    float s0 = 0.0f, s1 = 0.0f;
#pragma unroll
    for (int i = 0; i < 16; i++) {
        a0[i] = expf(a0[i] - mx0); s0 += a0[i];
        a1[i] = expf(a1[i] - mx1); s1 += a1[i];
    }
    float i0 = 1.0f / s0, i1 = 1.0f / s1;
    float acc0 = 0.0f, acc1 = 0.0f;
#pragma unroll
    for (int i = 0; i < 16; i++) {
        size_t vb = (size_t)kn[i]*COUT + c;
        float vp0 = g_vall[vb]     + g_pos[base + (size_t)i*COUT];
        float vp1 = g_vall[vb + 1] + g_pos[base + (size_t)i*COUT + 1];
        acc0 = fmaf(a0[i]*i0, vp0, acc0);
        acc1 = fmaf(a1[i]*i1, vp1, acc1);
    }
    uint32_t h, l;
    split2(acc0, acc1, h, l);
    *(uint32_t*)&g_r0h[(size_t)bs*COUT + c] = h;
    *(uint32_t*)&g_r0l[(size_t)bs*COUT + c] = l;
}

// ---------------------------- BatchNorm ------------------------------------
__global__ void bn_partial_kernel()
{
    int blk = blockIdx.x;
    int c   = threadIdx.x;
    float s = 0.0f, q = 0.0f;
    for (int r = blk*128; r < blk*128 + 128; r++) {
        float x = g_res1[(size_t)r*COUT + c];
        s += x; q = fmaf(x, x, q);
    }
    g_psum[blk*COUT + c] = s;
    g_psq [blk*COUT + c] = q;
}

__global__ void bn_final_kernel(const float* __restrict__ bng, const float* __restrict__ bnb)
{
    int c = threadIdx.x;
    float s = 0.0f, q = 0.0f;
    for (int i = 0; i < 64; i++) { s += g_psum[i*COUT + c]; q += g_psq[i*COUT + c]; }
    float mean = s * (1.0f/(float)BSR);
    float var  = fmaxf(q * (1.0f/(float)BSR) - mean*mean, 0.0f);
    float sc   = bng[c] * rsqrtf(var + 1e-5f);
    g_scale[c] = sc;
    g_shift[c] = bnb[c] - mean * sc;
}

__global__ void bn_apply_kernel(float* __restrict__ out)
{
    size_t e = (size_t)blockIdx.x * blockDim.x + threadIdx.x;
    int c = (int)(e & 255);
    out[e] = fmaxf(fmaf(g_res1[e], g_scale[c], g_shift[c]), 0.0f);
}

// ------------------------------ launch --------------------------------------
extern "C" void kernel_launch(void* const* d_in, const int* in_sizes, int n_in,
                              void* d_out, int out_size)
{
    const float* xyz    = (const float*)d_in[0];
    const float* points = (const float*)d_in[1];
    const float* wq     = (const float*)d_in[2];
    const float* wk     = (const float*)d_in[3];
    const float* wv     = (const float*)d_in[4];
    const float* dw1    = (const float*)d_in[5];
    const float* db1    = (const float*)d_in[6];
    const float* dw2    = (const float*)d_in[7];
    const float* db2    = (const float*)d_in[8];
    const float* gw1    = (const float*)d_in[9];
    const float* gb1    = (const float*)d_in[10];
    const float* gw2    = (const float*)d_in[11];
    const float* gb2    = (const float*)d_in[12];
    const float* lw     = (const float*)d_in[13];
    const float* lb     = (const float*)d_in[14];
    const float* bng    = (const float*)d_in[15];
    const float* bnb    = (const float*)d_in[16];

    float* out     = (float*)d_out;
    float* newxyz  = out;
    float* res_out = out + (size_t)BSR*3;

    static bool attr_set = false;
    if (!attr_set) {
        cudaFuncSetAttribute(tgemm_bf, cudaFuncAttributeMaxDynamicSharedMemorySize, TG_SMEM);
        attr_set = true;
    }

#define SYM(p, s) void* p; cudaGetSymbolAddress(&p, s)
    SYM(ppos, g_pos);  SYM(patt, g_att);
    SYM(pa1h, g_a1h);  SYM(pa1l, g_a1l);
    SYM(px1h, g_x1h);  SYM(px1l, g_x1l);
    SYM(pph,  g_ph);   SYM(ppl,  g_pl);
    SYM(pk,   g_kall); SYM(pv,   g_vall);
    SYM(pq,   g_q);
    SYM(pr0h, g_r0h);  SYM(pr0l, g_r0l);
    SYM(pr1,  g_res1);
    SYM(pfps, g_fps);  SYM(pknn, g_knn);
    SYM(pwkh, g_wkh);  SYM(pwkl, g_wkl);
    SYM(pwvh, g_wvh);  SYM(pwvl, g_wvl);
    SYM(pwqh, g_wqh);  SYM(pwql, g_wql);
    SYM(pdw2h, g_dw2h); SYM(pdw2l, g_dw2l);
    SYM(pgw1h, g_gw1h); SYM(pgw1l, g_gw1l);
    SYM(pgw2h, g_gw2h); SYM(pgw2l, g_gw2l);
    SYM(plwh, g_lwh);   SYM(plwl, g_lwl);
#undef SYM

    // 0. pre-split weights + points to bf16 hi/lo
    cvt_kernel<<<(NPTS*CIN)/512, 256>>>(points, (bf16*)pph, (bf16*)ppl, NPTS*CIN);
    cvt_kernel<<<(CIN*COUT)/512, 256>>>(wk,  (bf16*)pwkh,  (bf16*)pwkl,  CIN*COUT);
    cvt_kernel<<<(CIN*COUT)/512, 256>>>(wv,  (bf16*)pwvh,  (bf16*)pwvl,  CIN*COUT);
    cvt_kernel<<<(CIN*COUT)/512, 256>>>(wq,  (bf16*)pwqh,  (bf16*)pwql,  CIN*COUT);
    cvt_kernel<<<(COUT*COUT)/512, 256>>>(dw2, (bf16*)pdw2h, (bf16*)pdw2l, COUT*COUT);
    cvt_kernel<<<(COUT*COUT)/512, 256>>>(gw1, (bf16*)pgw1h, (bf16*)pgw1l, COUT*COUT);
    cvt_kernel<<<(COUT*COUT)/512, 256>>>(gw2, (bf16*)pgw2h, (bf16*)pgw2l, COUT*COUT);
    cvt_kernel<<<(COUT*COUT)/512, 256>>>(lw,  (bf16*)plwh,  (bf16*)plwl,  COUT*COUT);

    // 1. FPS (+ writes new_xyz)
    fps_kernel<<<BB, 256>>>(xyz, newxyz);
    // 2. KNN indices
    knn_kernel<<<BSR/8, 256>>>(xyz, newxyz);

    // 3/4. k_all / v_all = points @ wk/wv  (M=32768, Kd=128)
    tgemm_bf<<<dim3(COUT/64, NPTS/128), 256, TG_SMEM>>>(
        (const bf16*)pph, (const bf16*)ppl, nullptr,
        (const bf16*)pwkh, (const bf16*)pwkl, nullptr, CIN, 0,
        (float*)pk, nullptr, nullptr, nullptr, nullptr, nullptr, nullptr, nullptr);
    tgemm_bf<<<dim3(COUT/64, NPTS/128), 256, TG_SMEM>>>(
        (const bf16*)pph, (const bf16*)ppl, nullptr,
        (const bf16*)pwvh, (const bf16*)pwvl, nullptr, CIN, 0,
        (float*)pv, nullptr, nullptr, nullptr, nullptr, nullptr, nullptr, nullptr);
    // 5. q = gather(points, fps) @ wq  (M=8192)
    tgemm_bf<<<dim3(COUT/64, BSR/128), 256, TG_SMEM>>>(
        (const bf16*)pph, (const bf16*)ppl, (const int*)pfps,
        (const bf16*)pwqh, (const bf16*)pwql, nullptr, CIN, 0,
        (float*)pq, nullptr, nullptr, nullptr, nullptr, nullptr, nullptr, nullptr);
    // 6. pos-enc layer 1 -> x1 (bf16 split)
    h1_kernel<<<MROWS, 128>>>(xyz, newxyz, dw1, db1);
    // 7. pos = h1 @ dw2 + db2 -> g_pos (fp32);  fused a1 = q - k_gather + pos -> a1 hi/lo
    tgemm_bf<<<dim3(COUT/64, MROWS/128), 256, TG_SMEM>>>(
        (const bf16*)px1h, (const bf16*)px1l, nullptr,
        (const bf16*)pdw2h, (const bf16*)pdw2l, db2, COUT, 0,
        (float*)ppos, nullptr, nullptr,
        (const float*)pq, (const float*)pk, (const int*)pknn,
        (bf16*)pa1h, (bf16*)pa1l);
    // 8. h2 = relu(a1 @ gw1 + gb1) -> x1 hi/lo (h1 dead)
    tgemm_bf<<<dim3(COUT/64, MROWS/128), 256, TG_SMEM>>>(
        (const bf16*)pa1h, (const bf16*)pa1l, nullptr,
        (const bf16*)pgw1h, (const bf16*)pgw1l, gb1, COUT, 1,
        nullptr, (bf16*)px1h, (bf16*)px1l, nullptr, nullptr, nullptr, nullptr, nullptr);
    // 9. att = h2 @ gw2 + gb2 -> fp32
    tgemm_bf<<<dim3(COUT/64, MROWS/128), 256, TG_SMEM>>>(
        (const bf16*)px1h, (const bf16*)px1l, nullptr,
        (const bf16*)pgw2h, (const bf16*)pgw2l, gb2, COUT, 0,
        (float*)patt, nullptr, nullptr, nullptr, nullptr, nullptr, nullptr, nullptr);
    // 10. softmax over K + weighted sum of (v_gather + pos) -> res0 hi/lo
    softmax_reduce_kernel<<<BSR, 128>>>();
    // 11. res1 = res0 @ lw + lb
    tgemm_bf<<<dim3(COUT/64, BSR/128), 256, TG_SMEM>>>(
        (const bf16*)pr0h, (const bf16*)pr0l, nullptr,
        (const bf16*)plwh, (const bf16*)plwl, lb, COUT, 0,
        (float*)pr1, nullptr, nullptr, nullptr, nullptr, nullptr, nullptr, nullptr);
    // 12. BatchNorm (training stats) + ReLU -> output
    bn_partial_kernel<<<64, 256>>>();
    bn_final_kernel<<<1, 256>>>(bng, bnb);
    bn_apply_kernel<<<(BSR*COUT)/1024, 1024>>>(res_out);
}